// round 13
// baseline (speedup 1.0000x reference)
#include <cuda_runtime.h>
#include <cuda_fp16.h>
#include <math.h>
#include <stdint.h>

// ---------------------------------------------------------------------------
// Problem constants
// ---------------------------------------------------------------------------
#define CC     768
#define C3     2304
#define NH     12
#define HD     64
#define HIDDEN 3072
#define TT     8
#define HW     196
#define BB     4
#define NTOK   1569
#define MT     6272
#define MS     6304
#define MX     6276
#define SL     197
#define SB     32
#define ZB     (SB*NH)
#define KP     224          // padded K for P/Vt (7 * 32)

// ---------------------------------------------------------------------------
// Static device scratch
// ---------------------------------------------------------------------------
__device__ float g_xt  [(size_t)MT * CC];
__device__ float g_proj[(size_t)MS * CC];

// fp16 activations
__device__ __half g_ln_h[(size_t)MS * CC];
__device__ __half g_at_h[(size_t)MS * CC];
__device__ __half g_f1_h[(size_t)MX * HIDDEN];
__device__ __half g_qs_h[(size_t)MS * C3];     // qkv (temporal reuses, then spatial)
__device__ __half g_p_h [(size_t)ZB * SL * KP];
__device__ __half g_vt_h[(size_t)ZB * HD * KP];

// weights: single fp16
__device__ __half g_wtq [(size_t)C3 * CC];
__device__ __half g_wtf [(size_t)CC * CC];
__device__ __half g_wpT [(size_t)CC * CC];     // t_proj_w transposed (fp16)
__device__ __half g_wc  [(size_t)CC * CC];     // combined Wf @ Wp (fp16)
__device__ __half g_wsq [(size_t)C3 * CC];
__device__ __half g_wsp [(size_t)CC * CC];
__device__ __half g_wf1 [(size_t)HIDDEN * CC];
__device__ __half g_wf2 [(size_t)CC * HIDDEN];
__device__ float  g_bc  [CC];                  // combined bias
__device__ float  g_zb  [CC];                  // zero bias (static zero-init)

// ---------------------------------------------------------------------------
// Helpers
// ---------------------------------------------------------------------------
__device__ __forceinline__ float gelu_exact(float v) {
    return 0.5f * v * (1.0f + erff(v * 0.7071067811865475f));
}

__device__ __forceinline__ uint32_t smem_u32(const void* p) {
    uint32_t a;
    asm("{ .reg .u64 t; cvta.to.shared.u64 t, %1; cvt.u32.u64 %0, t; }" : "=r"(a) : "l"(p));
    return a;
}

__device__ __forceinline__ void cpasync16(uint32_t dst, const void* src) {
    asm volatile("cp.async.cg.shared.global [%0], [%1], 16;" :: "r"(dst), "l"(src));
}
#define CP_COMMIT() asm volatile("cp.async.commit_group;" ::: "memory")
#define CP_WAIT0()  asm volatile("cp.async.wait_group 0;" ::: "memory")
#define CP_WAIT1()  asm volatile("cp.async.wait_group 1;" ::: "memory")

__device__ __forceinline__ void ldm4(uint32_t* r, uint32_t addr) {
    asm volatile("ldmatrix.sync.aligned.m8n8.x4.shared.b16 {%0,%1,%2,%3}, [%4];"
                 : "=r"(r[0]), "=r"(r[1]), "=r"(r[2]), "=r"(r[3]) : "r"(addr));
}

__device__ __forceinline__ void mma16816(float* d, const uint32_t* a, const uint32_t* b) {
    asm volatile(
        "mma.sync.aligned.m16n8k16.row.col.f32.f16.f16.f32 "
        "{%0,%1,%2,%3}, {%4,%5,%6,%7}, {%8,%9}, {%0,%1,%2,%3};"
        : "+f"(d[0]), "+f"(d[1]), "+f"(d[2]), "+f"(d[3])
        : "r"(a[0]), "r"(a[1]), "r"(a[2]), "r"(a[3]), "r"(b[0]), "r"(b[1]));
}

// ---------------------------------------------------------------------------
// Single-chain fp16 HMMA NT GEMM: C = A(fp16) * B(fp16)^T + bias.
// CTA 128x128, 8 warps (64Mx32N), k-step 32, 3-stage cp.async (wait_group 1).
//   EPI 0: +bias   1: gelu(+bias)   2: +bias+resid(skip-cls)   3: +bias+C
//   OUT 0: fp32 C  1: fp16 (Ch)
// ---------------------------------------------------------------------------
#define STG    20480u
#define OFF_A  0u
#define OFF_B  10240u
#define GEMM_SMEM (3 * STG)

template<int EPI, int OUT>
__global__ void __launch_bounds__(256, 2)
gemm_mma(const __half* __restrict__ Ahg,
         const __half* __restrict__ Bg,
         const float* __restrict__ bias,
         float* __restrict__ C,
         __half* __restrict__ Ch,
         const float* __restrict__ resid,
         int M, int N, int K)
{
    extern __shared__ char smem[];
    const uint32_t sb = smem_u32(smem);

    const int tid  = threadIdx.x;
    const int wid  = tid >> 5;
    const int lane = tid & 31;
    const int row0 = blockIdx.y * 128;
    const int col0 = blockIdx.x * 128;
    const int KT   = K >> 5;

    float acc[4][4][4];
    #pragma unroll
    for (int a = 0; a < 4; a++)
        #pragma unroll
        for (int b = 0; b < 4; b++)
            #pragma unroll
            for (int c = 0; c < 4; c++) acc[a][b][c] = 0.0f;

    auto load_stage = [&](int kt, int buf) {
        const int kw = kt * 32;
        const uint32_t dstb = sb + buf * STG;
        #pragma unroll
        for (int q = 0; q < 2; q++) {
            int cid = q * 256 + tid;
            int row = cid >> 2, ch = cid & 3;
            int ar  = min(row0 + row, M - 1);
            cpasync16(dstb + OFF_A + row * 80u + ch * 16u,
                      Ahg + (size_t)ar * K + kw + ch * 8);
        }
        #pragma unroll
        for (int q = 0; q < 2; q++) {
            int cid = q * 256 + tid;
            int row = cid >> 2, ch = cid & 3;
            cpasync16(dstb + OFF_B + row * 80u + ch * 16u,
                      Bg + (size_t)(col0 + row) * K + kw + ch * 8);
        }
        CP_COMMIT();
    };

    load_stage(0, 0);
    load_stage(1, 1);
    CP_WAIT1();
    __syncthreads();

    const int m0w = (wid & 1) * 64;
    const int n0w = (wid >> 1) * 32;
    const uint32_t a_off = (uint32_t)(m0w + (lane & 15)) * 80u + (uint32_t)((lane >> 4) << 4);
    const uint32_t b_off = (uint32_t)(n0w + (lane & 7) + ((lane >> 4) << 3)) * 80u
                         + (uint32_t)(((lane >> 3) & 1) << 4);

    for (int kt = 0; kt < KT; kt++) {
        const int buf = kt % 3;
        const uint32_t bb = sb + buf * STG;
        #pragma unroll
        for (int s = 0; s < 2; s++) {
            uint32_t ah[4][4], bh[4][2];
            #pragma unroll
            for (int mi = 0; mi < 4; mi++)
                ldm4(ah[mi], bb + OFF_A + a_off + mi * 1280u + s * 32u);
            #pragma unroll
            for (int nj = 0; nj < 2; nj++) {
                uint32_t t[4];
                ldm4(t, bb + OFF_B + b_off + nj * 1280u + s * 32u);
                bh[nj*2][0] = t[0]; bh[nj*2][1] = t[1];
                bh[nj*2+1][0] = t[2]; bh[nj*2+1][1] = t[3];
            }
            #pragma unroll
            for (int mi = 0; mi < 4; mi++)
                #pragma unroll
                for (int nj = 0; nj < 4; nj++)
                    mma16816(acc[mi][nj], ah[mi], bh[nj]);
        }
        if (kt + 2 < KT) {
            load_stage(kt + 2, (kt + 2) % 3);
            CP_WAIT1();
        } else {
            CP_WAIT0();
        }
        __syncthreads();
    }

    #pragma unroll
    for (int mi = 0; mi < 4; mi++) {
        const int rbase = row0 + m0w + mi * 16 + (lane >> 2);
        #pragma unroll
        for (int half = 0; half < 2; half++) {
            const int m = rbase + half * 8;
            if (m >= M) continue;
            #pragma unroll
            for (int nj = 0; nj < 4; nj++) {
                const int n = col0 + n0w + nj * 8 + (lane & 3) * 2;
                float v0 = acc[mi][nj][half * 2 + 0] + bias[n];
                float v1 = acc[mi][nj][half * 2 + 1] + bias[n + 1];
                if (EPI == 1) { v0 = gelu_exact(v0); v1 = gelu_exact(v1); }
                if (EPI == 2) {
                    const float* rs = resid + (size_t)(m + m / 1568 + 1) * CC + n;
                    v0 += rs[0]; v1 += rs[1];
                }
                if (OUT == 0) {
                    float* cp = C + (size_t)m * N + n;
                    if (EPI == 3) {
                        float2 old = *(const float2*)cp;
                        v0 += old.x; v1 += old.y;
                    }
                    float2 o = {v0, v1};
                    *(float2*)cp = o;
                } else {
                    *(__half2*)(Ch + (size_t)m * N + n) =
                        __halves2half2(__float2half_rn(v0), __float2half_rn(v1));
                }
            }
        }
    }
}

// ---------------------------------------------------------------------------
// FUSED spatial scores + softmax (1-chain fp16) — Round-12, passing.
// ---------------------------------------------------------------------------
#define FSTG     28160u
#define FOFF_A   0u
#define FOFF_B   10240u
#define FSC_SMEM (2 * FSTG)

__global__ void __launch_bounds__(256)
attn_scores_softmax(const __half* __restrict__ qh, __half* __restrict__ ph)
{
    extern __shared__ char smem[];
    const uint32_t sb = smem_u32(smem);

    const int z = blockIdx.y;
    const int s = z / NH, h = z % NH;
    const size_t base  = (size_t)(s * SL) * C3 + h * HD;
    const size_t pbase = (size_t)z * SL * KP;

    const int tid  = threadIdx.x;
    const int wid  = tid >> 5;
    const int lane = tid & 31;
    const int row0 = blockIdx.x * 128;

    #pragma unroll
    for (int kt = 0; kt < 2; kt++) {
        const int kw = kt * 32;
        const uint32_t dstb = sb + kt * FSTG;
        #pragma unroll
        for (int q = 0; q < 2; q++) {
            int cid = q * 256 + tid;
            int row = cid >> 2, ch = cid & 3;
            int gr  = min(row0 + row, SL - 1);
            cpasync16(dstb + FOFF_A + row * 80u + ch * 16u,
                      qh + base + (size_t)gr * C3 + kw + ch * 8);
        }
        #pragma unroll
        for (int q = 0; q < 4; q++) {
            int cid = q * 256 + tid;
            if (cid < 896) {
                int row = cid >> 2, ch = cid & 3;
                int gr  = min(row, SL - 1);
                cpasync16(dstb + FOFF_B + row * 80u + ch * 16u,
                          qh + base + (size_t)gr * C3 + CC + kw + ch * 8);
            }
        }
        CP_COMMIT();
    }
    CP_WAIT0();
    __syncthreads();

    const int m0w = wid * 16;
    const uint32_t a_off = (uint32_t)(m0w + (lane & 15)) * 80u + (uint32_t)((lane >> 4) << 4);
    const uint32_t b_off = (uint32_t)((lane & 7) + ((lane >> 4) << 3)) * 80u
                         + (uint32_t)(((lane >> 3) & 1) << 4);

    float acc[28][4];
    #pragma unroll
    for (int t = 0; t < 28; t++)
        #pragma unroll
        for (int c = 0; c < 4; c++) acc[t][c] = 0.0f;

    #pragma unroll
    for (int kt = 0; kt < 2; kt++) {
        const uint32_t bb = sb + kt * FSTG;
        #pragma unroll
        for (int s2 = 0; s2 < 2; s2++) {
            uint32_t ah[4];
            ldm4(ah, bb + FOFF_A + a_off + s2 * 32u);
            #pragma unroll
            for (int njq = 0; njq < 14; njq++) {
                uint32_t th[4];
                ldm4(th, bb + FOFF_B + b_off + njq * 1280u + s2 * 32u);
                uint32_t b0[2] = {th[0], th[1]}, b1[2] = {th[2], th[3]};
                mma16816(acc[njq*2],   ah, b0);
                mma16816(acc[njq*2+1], ah, b1);
            }
        }
    }

    const int ncol0 = (lane & 3) * 2;
    #pragma unroll
    for (int half = 0; half < 2; half++) {
        const int row = row0 + m0w + (lane >> 2) + half * 8;
        float mx = -1e30f;
        #pragma unroll
        for (int t = 0; t < 28; t++) {
            int n = t * 8 + ncol0;
            float v0 = acc[t][half*2+0] * 0.125f;
            float v1 = acc[t][half*2+1] * 0.125f;
            acc[t][half*2+0] = (n < SL)     ? v0 : -1e30f;
            acc[t][half*2+1] = (n + 1 < SL) ? v1 : -1e30f;
            mx = fmaxf(mx, acc[t][half*2+0]);
            mx = fmaxf(mx, acc[t][half*2+1]);
        }
        mx = fmaxf(mx, __shfl_xor_sync(0xffffffffu, mx, 1));
        mx = fmaxf(mx, __shfl_xor_sync(0xffffffffu, mx, 2));
        float sum = 0.0f;
        #pragma unroll
        for (int t = 0; t < 28; t++) {
            float e0 = expf(acc[t][half*2+0] - mx);
            float e1 = expf(acc[t][half*2+1] - mx);
            int n = t * 8 + ncol0;
            e0 = (n < SL)     ? e0 : 0.0f;
            e1 = (n + 1 < SL) ? e1 : 0.0f;
            acc[t][half*2+0] = e0;
            acc[t][half*2+1] = e1;
            sum += e0 + e1;
        }
        sum += __shfl_xor_sync(0xffffffffu, sum, 1);
        sum += __shfl_xor_sync(0xffffffffu, sum, 2);
        float inv = 1.0f / sum;
        if (row < SL) {
            size_t ob = pbase + (size_t)row * KP;
            #pragma unroll
            for (int t = 0; t < 28; t++) {
                int n = t * 8 + ncol0;
                *(__half2*)(ph + ob + n) = __halves2half2(
                    __float2half_rn(acc[t][half*2+0] * inv),
                    __float2half_rn(acc[t][half*2+1] * inv));
            }
        }
    }
}

// ---------------------------------------------------------------------------
// Batched PV via HMMA (1-chain fp16) — Round-12, passing.
// ---------------------------------------------------------------------------
#define PSTG    15360u
#define POFF_A  0u
#define POFF_B  10240u
#define PV_SMEM (2 * PSTG)

__global__ void __launch_bounds__(256)
attn_pv_mma(const __half* __restrict__ ph,
            const __half* __restrict__ vth,
            __half* __restrict__ oh)
{
    extern __shared__ char smem[];
    const uint32_t sb = smem_u32(smem);

    const int z = blockIdx.y;
    const int s = z / NH, h = z % NH;
    const size_t pbase = (size_t)z * SL * KP;
    const size_t vbase = (size_t)z * HD * KP;

    const int tid  = threadIdx.x;
    const int wid  = tid >> 5;
    const int lane = tid & 31;
    const int row0 = blockIdx.x * 128;

    float acc[2][4][4];
    #pragma unroll
    for (int a = 0; a < 2; a++)
        #pragma unroll
        for (int b = 0; b < 4; b++)
            #pragma unroll
            for (int c = 0; c < 4; c++) acc[a][b][c] = 0.0f;

    auto load_stage = [&](int kt, int buf) {
        const int kw = kt * 32;
        const uint32_t dstb = sb + buf * PSTG;
        #pragma unroll
        for (int q = 0; q < 2; q++) {
            int cid = q * 256 + tid;
            int row = cid >> 2, ch = cid & 3;
            int gr  = min(row0 + row, SL - 1);
            cpasync16(dstb + POFF_A + row * 80u + ch * 16u,
                      ph + pbase + (size_t)gr * KP + kw + ch * 8);
        }
        {
            int row = tid >> 2, ch = tid & 3;
            cpasync16(dstb + POFF_B + row * 80u + ch * 16u,
                      vth + vbase + (size_t)row * KP + kw + ch * 8);
        }
        CP_COMMIT();
    };

    load_stage(0, 0);
    CP_WAIT0();
    __syncthreads();

    const int m0w = (wid & 3) * 32;
    const int n0w = (wid >> 2) * 32;
    const uint32_t a_off = (uint32_t)(m0w + (lane & 15)) * 80u + (uint32_t)((lane >> 4) << 4);
    const uint32_t b_off = (uint32_t)(n0w + (lane & 7) + ((lane >> 4) << 3)) * 80u
                         + (uint32_t)(((lane >> 3) & 1) << 4);

    for (int kt = 0; kt < KP / 32; kt++) {
        const int buf = kt & 1;
        if (kt + 1 < KP / 32) load_stage(kt + 1, buf ^ 1);

        const uint32_t bb = sb + buf * PSTG;
        #pragma unroll
        for (int s2 = 0; s2 < 2; s2++) {
            uint32_t ah[2][4], bh[4][2];
            #pragma unroll
            for (int mi = 0; mi < 2; mi++)
                ldm4(ah[mi], bb + POFF_A + a_off + mi * 1280u + s2 * 32u);
            #pragma unroll
            for (int nj = 0; nj < 2; nj++) {
                uint32_t t[4];
                ldm4(t, bb + POFF_B + b_off + nj * 1280u + s2 * 32u);
                bh[nj*2][0] = t[0]; bh[nj*2][1] = t[1];
                bh[nj*2+1][0] = t[2]; bh[nj*2+1][1] = t[3];
            }
            #pragma unroll
            for (int mi = 0; mi < 2; mi++)
                #pragma unroll
                for (int nj = 0; nj < 4; nj++)
                    mma16816(acc[mi][nj], ah[mi], bh[nj]);
        }
        CP_WAIT0();
        __syncthreads();
    }

    #pragma unroll
    for (int mi = 0; mi < 2; mi++) {
        const int rbase = row0 + m0w + mi * 16 + (lane >> 2);
        #pragma unroll
        for (int half = 0; half < 2; half++) {
            const int m = rbase + half * 8;
            if (m >= SL) continue;
            size_t ob = (size_t)(s * SL + m) * CC + h * HD;
            #pragma unroll
            for (int nj = 0; nj < 4; nj++) {
                const int n = n0w + nj * 8 + (lane & 3) * 2;
                *(__half2*)(oh + ob + n) = __halves2half2(
                    __float2half_rn(acc[mi][nj][half * 2 + 0]),
                    __float2half_rn(acc[mi][nj][half * 2 + 1]));
            }
        }
    }
}

// ---------------------------------------------------------------------------
// V transpose: per z, Vt[d][t] = V[t][d], padded t->224 with zeros.
// ---------------------------------------------------------------------------
__global__ void transpose_v(const __half* __restrict__ qh, __half* __restrict__ vth)
{
    int z = blockIdx.x;
    int s = z / NH, h = z % NH;
    size_t vbase = (size_t)(s * SL) * C3 + 2 * CC + h * HD;
    size_t obase = (size_t)z * HD * KP;
    __shared__ __half shh[32][66];
    int tid = threadIdx.x;

    for (int t0 = 0; t0 < KP; t0 += 32) {
        #pragma unroll
        for (int i = 0; i < 8; i++) {
            int e = i * 256 + tid;
            int t = e >> 6, d = e & 63;
            int gt = t0 + t;
            shh[t][d] = (gt < SL) ? qh[vbase + (size_t)gt * C3 + d]
                                  : __float2half(0.0f);
        }
        __syncthreads();
        #pragma unroll
        for (int i = 0; i < 8; i++) {
            int e = i * 256 + tid;
            int d = e >> 5, t = e & 31;
            vth[obase + (size_t)d * KP + t0 + t] = shh[t][d];
        }
        __syncthreads();
    }
}

// ---------------------------------------------------------------------------
// Weight transpose (fp32 -> fp16 transposed): wt[n][j] = w[j][n]. 768x768.
// ---------------------------------------------------------------------------
__global__ void transpose_w(const float* __restrict__ w, __half* __restrict__ wt)
{
    __shared__ float tile[32][33];
    int bx = blockIdx.x * 32, by = blockIdx.y * 32;
    int tx = threadIdx.x & 31, ty = threadIdx.x >> 5;   // 32 x 8
    #pragma unroll
    for (int r = 0; r < 32; r += 8)
        tile[ty + r][tx] = w[(size_t)(by + ty + r) * CC + bx + tx];
    __syncthreads();
    #pragma unroll
    for (int r = 0; r < 32; r += 8)
        wt[(size_t)(bx + ty + r) * CC + by + tx] = __float2half_rn(tile[tx][ty + r]);
}

// ---------------------------------------------------------------------------
// Combined bias: bc[i] = bf[i] + sum_j Wf[i,j] * bp[j]. grid=768, 256 thr.
// ---------------------------------------------------------------------------
__global__ void combine_bias(const float* __restrict__ wf, const float* __restrict__ bp,
                             const float* __restrict__ bf, float* __restrict__ bc)
{
    int i = blockIdx.x;
    int tid = threadIdx.x;
    float s = 0.0f;
    for (int j = tid; j < CC; j += 256)
        s += wf[(size_t)i * CC + j] * bp[j];
    __shared__ float sh[32];
    int lane = tid & 31, wid = tid >> 5;
    #pragma unroll
    for (int o = 16; o; o >>= 1) s += __shfl_xor_sync(0xffffffffu, s, o);
    if (lane == 0) sh[wid] = s;
    __syncthreads();
    if (tid == 0) {
        float t = 0.0f;
        #pragma unroll
        for (int wq = 0; wq < 8; wq++) t += sh[wq];
        bc[i] = t + bf[i];
    }
}

// ---------------------------------------------------------------------------
// Fused weight conversion: 6 weights -> single fp16, one launch.
// ---------------------------------------------------------------------------
struct WSegs {
    const float4* src[6];
    __half2*      dh[6];
    int           n4[6];
};

__global__ void conv_all(WSegs w, int total4)
{
    int i = blockIdx.x * blockDim.x + threadIdx.x;
    if (i >= total4) return;
    int rem = i;
    #pragma unroll
    for (int s = 0; s < 6; s++) {
        if (rem < w.n4[s]) {
            float4 v = w.src[s][rem];
            w.dh[s][rem * 2 + 0] = __halves2half2(__float2half_rn(v.x), __float2half_rn(v.y));
            w.dh[s][rem * 2 + 1] = __halves2half2(__float2half_rn(v.z), __float2half_rn(v.w));
            return;
        }
        rem -= w.n4[s];
    }
}

// ---------------------------------------------------------------------------
// LN core: values v0,v1,v2 per thread. Writes fp16.
// ---------------------------------------------------------------------------
__device__ __forceinline__ void ln_core(float v0, float v1, float v2,
                                        const float* __restrict__ g,
                                        const float* __restrict__ bta,
                                        __half* __restrict__ oh, size_t ob)
{
    int tid = threadIdx.x;
    int lane = tid & 31, wid = tid >> 5;
    __shared__ float sh[32];
    float s = v0 + v1 + v2;
    #pragma unroll
    for (int o = 16; o; o >>= 1) s += __shfl_xor_sync(0xffffffffu, s, o);
    if (lane == 0) sh[wid] = s;
    __syncthreads();
    if (wid == 0) {
        float t2 = (lane < 8) ? sh[lane] : 0.0f;
        #pragma unroll
        for (int o = 4; o; o >>= 1) t2 += __shfl_xor_sync(0xffffffffu, t2, o);
        if (lane == 0) sh[0] = t2;
    }
    __syncthreads();
    float mean = sh[0] * (1.0f / 768.0f);
    __syncthreads();
    float d0 = v0 - mean, d1 = v1 - mean, d2 = v2 - mean;
    float s2 = d0 * d0 + d1 * d1 + d2 * d2;
    #pragma unroll
    for (int o = 16; o; o >>= 1) s2 += __shfl_xor_sync(0xffffffffu, s2, o);
    if (lane == 0) sh[wid] = s2;
    __syncthreads();
    if (wid == 0) {
        float t2 = (lane < 8) ? sh[lane] : 0.0f;
        #pragma unroll
        for (int o = 4; o; o >>= 1) t2 += __shfl_xor_sync(0xffffffffu, t2, o);
        if (lane == 0) sh[0] = t2;
    }
    __syncthreads();
    float inv = rsqrtf(sh[0] * (1.0f / 768.0f) + 1e-5f);
    #pragma unroll
    for (int p = 0; p < 3; p++) {
        float d = (p == 0) ? d0 : (p == 1) ? d1 : d2;
        int c = tid + p * 256;
        oh[ob + c] = __float2half_rn(d * inv * g[c] + bta[c]);
    }
}

// ---------------------------------------------------------------------------
// LayerNorm (modes 0/1 gather). One block/row. Writes fp16.
// ---------------------------------------------------------------------------
__global__ void ln_kernel(const float* __restrict__ src0,
                          const float* __restrict__ xt,
                          const float* __restrict__ g,
                          const float* __restrict__ bta,
                          __half* __restrict__ oh, int mode)
{
    int m = blockIdx.x;
    const float* src;
    if (mode == 0) {
        src = src0 + (size_t)(m + m / 1568 + 1) * CC;
    } else {
        int sb = m / SL, p = m % SL;
        int b = sb >> 3, t = sb & 7;
        if (p == 0) src = src0 + (size_t)b * NTOK * CC;
        else        src = xt + ((size_t)(b * HW + (p - 1)) * TT + t) * CC;
    }
    int tid = threadIdx.x;
    float v0 = src[tid], v1 = src[tid + 256], v2 = src[tid + 512];
    ln_core(v0, v1, v2, g, bta, oh, (size_t)m * CC);
}

// ---------------------------------------------------------------------------
// Fused assemble + LN2.
// ---------------------------------------------------------------------------
__global__ void assemble_ln(const float* __restrict__ x, const float* __restrict__ xt,
                            const float* __restrict__ ps,
                            const float* __restrict__ g, const float* __restrict__ bta,
                            float* __restrict__ out,
                            __half* __restrict__ oh)
{
    int row = blockIdx.x;
    int b = row / NTOK, n = row % NTOK;
    size_t orow = (size_t)row * CC;
    int tid = threadIdx.x;
    float v[3];
    if (n == 0) {
        #pragma unroll
        for (int p = 0; p < 3; p++) {
            int c = tid + p * 256;
            float acc = 0.0f;
            #pragma unroll
            for (int t = 0; t < TT; t++)
                acc += ps[((size_t)(b * TT + t) * SL) * CC + c];
            v[p] = x[orow + c] + acc * 0.125f;
        }
    } else {
        int r = n - 1, hw = r >> 3, t = r & 7;
        size_t xtrow = ((size_t)b * 1568 + r) * CC;
        size_t psrow = ((size_t)((b * TT + t) * SL + 1 + hw)) * CC;
        #pragma unroll
        for (int p = 0; p < 3; p++) {
            int c = tid + p * 256;
            v[p] = xt[xtrow + c] + ps[psrow + c];
        }
    }
    #pragma unroll
    for (int p = 0; p < 3; p++)
        out[orow + tid + p * 256] = v[p];
    ln_core(v[0], v[1], v[2], g, bta, oh, orow);
}

// ---------------------------------------------------------------------------
// Temporal attention: fused per (seq, head), fp16 qkv input, fp16 output.
// ---------------------------------------------------------------------------
__global__ void temporal_attn(const __half* __restrict__ qkv,
                              __half* __restrict__ oh)
{
    int seq = blockIdx.x, h = blockIdx.y;
    __shared__ float q[TT][68], k[TT][68], v[TT][68];
    __shared__ float p[TT][TT];
    int tid = threadIdx.x;
    size_t base = (size_t)(seq * TT) * C3 + h * HD;

    // 64 threads: each loads one 8-half chunk per array (8t x 8 chunks)
    {
        int t = tid >> 3, d8 = (tid & 7) << 3;
        #pragma unroll
        for (int arr = 0; arr < 3; arr++) {
            float (*dst)[68] = (arr == 0) ? q : (arr == 1) ? k : v;
            float4 raw = *(const float4*)(qkv + base + (size_t)t * C3 + arr * CC + d8);
            const __half2* hp = (const __half2*)&raw;
            #pragma unroll
            for (int u = 0; u < 4; u++) {
                float2 f = __half22float2(hp[u]);
                dst[t][d8 + u * 2]     = f.x;
                dst[t][d8 + u * 2 + 1] = f.y;
            }
        }
    }
    __syncthreads();
    int i = tid >> 3, j = tid & 7;
    float s = 0.0f;
    #pragma unroll
    for (int d = 0; d < HD; d++) s = fmaf(q[i][d], k[j][d], s);
    p[i][j] = s * 0.125f;
    __syncthreads();
    if (tid < TT) {
        float mx = -1e30f;
        #pragma unroll
        for (int jj = 0; jj < TT; jj++) mx = fmaxf(mx, p[tid][jj]);
        float sum = 0.0f;
        #pragma unroll
        for (int jj = 0; jj < TT; jj++) {
            float e = expf(p[tid][jj] - mx);
            p[tid][jj] = e; sum += e;
        }
        float invs = 1.0f / sum;
        #pragma unroll
        for (int jj = 0; jj < TT; jj++) p[tid][jj] *= invs;
    }
    __syncthreads();
    #pragma unroll
    for (int t = 0; t < TT; t++) {
        float o = 0.0f;
        #pragma unroll
        for (int jj = 0; jj < TT; jj++) o = fmaf(p[t][jj], v[jj][tid], o);
        oh[(size_t)(seq * TT + t) * CC + h * HD + tid] = __float2half_rn(o);
    }
}

// ---------------------------------------------------------------------------
// Host launch
// ---------------------------------------------------------------------------
extern "C" void kernel_launch(void* const* d_in, const int* in_sizes, int n_in,
                              void* d_out, int out_size)
{
    const float* x        = (const float*)d_in[0];
    const float* ln_t_g   = (const float*)d_in[1];
    const float* ln_t_b   = (const float*)d_in[2];
    const float* t_qkv_w  = (const float*)d_in[3];
    const float* t_qkv_b  = (const float*)d_in[4];
    const float* t_proj_w = (const float*)d_in[5];
    const float* t_proj_b = (const float*)d_in[6];
    const float* t_fc_w   = (const float*)d_in[7];
    const float* t_fc_b   = (const float*)d_in[8];
    const float* ln1_g    = (const float*)d_in[9];
    const float* ln1_b    = (const float*)d_in[10];
    const float* s_qkv_w  = (const float*)d_in[11];
    const float* s_qkv_b  = (const float*)d_in[12];
    const float* s_proj_w = (const float*)d_in[13];
    const float* s_proj_b = (const float*)d_in[14];
    const float* ln2_g    = (const float*)d_in[15];
    const float* ln2_b    = (const float*)d_in[16];
    const float* fc1_w    = (const float*)d_in[17];
    const float* fc1_b    = (const float*)d_in[18];
    const float* fc2_w    = (const float*)d_in[19];
    const float* fc2_b    = (const float*)d_in[20];
    float* out = (float*)d_out;

    float *xt, *proj, *bc, *zb;
    __half *lnh, *ath, *f1h, *qsh, *ph, *vth;
    cudaGetSymbolAddress((void**)&xt,   g_xt);
    cudaGetSymbolAddress((void**)&proj, g_proj);
    cudaGetSymbolAddress((void**)&bc,   g_bc);
    cudaGetSymbolAddress((void**)&zb,   g_zb);
    cudaGetSymbolAddress((void**)&lnh,  g_ln_h);
    cudaGetSymbolAddress((void**)&ath,  g_at_h);
    cudaGetSymbolAddress((void**)&f1h,  g_f1_h);
    cudaGetSymbolAddress((void**)&qsh,  g_qs_h);
    cudaGetSymbolAddress((void**)&ph,   g_p_h);
    cudaGetSymbolAddress((void**)&vth,  g_vt_h);

    __half *wtq, *wtf, *wpT, *wc, *wsq, *wsp, *wf1, *wf2;
    cudaGetSymbolAddress((void**)&wtq, g_wtq);
    cudaGetSymbolAddress((void**)&wtf, g_wtf);
    cudaGetSymbolAddress((void**)&wpT, g_wpT);
    cudaGetSymbolAddress((void**)&wc,  g_wc);
    cudaGetSymbolAddress((void**)&wsq, g_wsq);
    cudaGetSymbolAddress((void**)&wsp, g_wsp);
    cudaGetSymbolAddress((void**)&wf1, g_wf1);
    cudaGetSymbolAddress((void**)&wf2, g_wf2);

    cudaFuncSetAttribute(gemm_mma<0,0>, cudaFuncAttributeMaxDynamicSharedMemorySize, GEMM_SMEM);
    cudaFuncSetAttribute(gemm_mma<0,1>, cudaFuncAttributeMaxDynamicSharedMemorySize, GEMM_SMEM);
    cudaFuncSetAttribute(gemm_mma<1,1>, cudaFuncAttributeMaxDynamicSharedMemorySize, GEMM_SMEM);
    cudaFuncSetAttribute(gemm_mma<2,0>, cudaFuncAttributeMaxDynamicSharedMemorySize, GEMM_SMEM);
    cudaFuncSetAttribute(gemm_mma<3,0>, cudaFuncAttributeMaxDynamicSharedMemorySize, GEMM_SMEM);
    cudaFuncSetAttribute(attn_scores_softmax, cudaFuncAttributeMaxDynamicSharedMemorySize, FSC_SMEM);
    cudaFuncSetAttribute(attn_pv_mma, cudaFuncAttributeMaxDynamicSharedMemorySize, PV_SMEM);

    // 0a. convert 6 weights (single fp16)
    {
        WSegs w;
        w.src[0] = (const float4*)t_qkv_w;  w.dh[0] = (__half2*)wtq; w.n4[0] = C3 * CC / 4;
        w.src[1] = (const float4*)t_fc_w;   w.dh[1] = (__half2*)wtf; w.n4[1] = CC * CC / 4;
        w.src[2] = (const float4*)s_qkv_w;  w.dh[2] = (__half2*)wsq; w.n4[2] = C3 * CC / 4;
        w.src[3] = (const float4*)s_proj_w; w.dh[3] = (__half2*)wsp; w.n4[3] = CC * CC / 4;
        w.src[4] = (const float4*)fc1_w;    w.dh[4] = (__half2*)wf1; w.n4[4] = HIDDEN * CC / 4;
        w.src[5] = (const float4*)fc2_w;    w.dh[5] = (__half2*)wf2; w.n4[5] = CC * HIDDEN / 4;
        int total4 = 0;
        for (int i = 0; i < 6; i++) total4 += w.n4[i];
        conv_all<<<(total4 + 255) / 256, 256>>>(w, total4);
    }
    // 0b. transpose t_proj_w -> fp16; combined bias; combined weight Wc = Wf @ Wp
    transpose_w<<<dim3(24, 24), 256>>>(t_proj_w, wpT);
    combine_bias<<<CC, 256>>>(t_fc_w, t_proj_b, t_fc_b, bc);
    gemm_mma<0,1><<<dim3(CC/128, CC/128), 256, GEMM_SMEM>>>(
        wtf, wpT, zb, nullptr, wc, nullptr, CC, CC, CC);

    // 1. temporal LN (skip cls) -> fp16
    ln_kernel<<<MT, 256>>>(x, nullptr, ln_t_g, ln_t_b, lnh, 0);

    // 2. temporal qkv -> fp16 (reuses spatial qkv buffer)
    gemm_mma<0,1><<<dim3(C3/128, (MT+127)/128), 256, GEMM_SMEM>>>(
        lnh, wtq, t_qkv_b, nullptr, qsh, nullptr, MT, C3, CC);

    // 3. temporal attention -> fp16
    temporal_attn<<<dim3(BB * HW, NH), 64>>>(qsh, ath);

    // 4. combined proj+fc + residual from x (skip-cls) -> fp32 xt
    gemm_mma<2,0><<<dim3(CC/128, (MT+127)/128), 256, GEMM_SMEM>>>(
        ath, wc, bc, xt, nullptr, x, MT, CC, CC);

    // 5. spatial gather + LN1 -> fp16
    ln_kernel<<<MS, 256>>>(x, xt, ln1_g, ln1_b, lnh, 1);

    // 6. spatial qkv -> fp16
    gemm_mma<0,1><<<dim3(C3/128, (MS+127)/128), 256, GEMM_SMEM>>>(
        lnh, wsq, s_qkv_b, nullptr, qsh, nullptr, MS, C3, CC);

    // 7-9. spatial attention (tensor cores, 1-chain fp16)
    attn_scores_softmax<<<dim3(2, ZB), 256, FSC_SMEM>>>(qsh, ph);
    transpose_v<<<ZB, 256>>>(qsh, vth);
    attn_pv_mma<<<dim3(2, ZB), 256, PV_SMEM>>>(ph, vth, ath);

    // 10. spatial proj -> fp32
    gemm_mma<0,0><<<dim3(CC/128, (MS+127)/128), 256, GEMM_SMEM>>>(
        ath, wsp, s_proj_b, proj, nullptr, nullptr, MS, CC, CC);

    // 11+12. assemble x_new into d_out AND LN2 -> fp16 (fused)
    assemble_ln<<<MX, 256>>>(x, xt, proj, ln2_g, ln2_b, out, lnh);

    // 13. fc1 + gelu -> fp16
    gemm_mma<1,1><<<dim3(HIDDEN/128, (MX+127)/128), 256, GEMM_SMEM>>>(
        lnh, wf1, fc1_b, nullptr, f1h, nullptr, MX, HIDDEN, CC);

    // 14. fc2 + in-place residual on d_out
    gemm_mma<3,0><<<dim3(CC/128, (MX+127)/128), 256, GEMM_SMEM>>>(
        f1h, wf2, fc2_b, out, nullptr, nullptr, MX, CC, HIDDEN);
}

// round 14
// speedup vs baseline: 1.0253x; 1.0253x over previous
#include <cuda_runtime.h>
#include <cuda_fp16.h>
#include <math.h>
#include <stdint.h>

// ---------------------------------------------------------------------------
// Problem constants
// ---------------------------------------------------------------------------
#define CC     768
#define C3     2304
#define NH     12
#define HD     64
#define HIDDEN 3072
#define TT     8
#define HW     196
#define BB     4
#define NTOK   1569
#define MT     6272
#define MS     6304
#define MX     6276
#define SL     197
#define SB     32
#define ZB     (SB*NH)
#define KP     224          // padded K for P/Vt (7 * 32)

// ---------------------------------------------------------------------------
// Static device scratch
// ---------------------------------------------------------------------------
__device__ float g_xt [(size_t)MT * CC];

// fp16 activations
__device__ __half g_ln_h[(size_t)MS * CC];
__device__ __half g_at_h[(size_t)MS * CC];
__device__ __half g_pj_h[(size_t)MT * CC];
__device__ __half g_f1_h[(size_t)MX * HIDDEN];
__device__ __half g_qs_h[(size_t)MS * C3];     // qkv (temporal, then spatial, then proj out)
__device__ __half g_p_h [(size_t)ZB * SL * KP];
__device__ __half g_vt_h[(size_t)ZB * HD * KP];

// weights: single fp16
__device__ __half g_wtq [(size_t)C3 * CC];
__device__ __half g_wtp [(size_t)CC * CC];
__device__ __half g_wtf [(size_t)CC * CC];
__device__ __half g_wsq [(size_t)C3 * CC];
__device__ __half g_wsp [(size_t)CC * CC];
__device__ __half g_wf1 [(size_t)HIDDEN * CC];
__device__ __half g_wf2 [(size_t)CC * HIDDEN];

// ---------------------------------------------------------------------------
// Helpers
// ---------------------------------------------------------------------------
__device__ __forceinline__ float gelu_exact(float v) {
    return 0.5f * v * (1.0f + erff(v * 0.7071067811865475f));
}

__device__ __forceinline__ uint32_t smem_u32(const void* p) {
    uint32_t a;
    asm("{ .reg .u64 t; cvta.to.shared.u64 t, %1; cvt.u32.u64 %0, t; }" : "=r"(a) : "l"(p));
    return a;
}

__device__ __forceinline__ void cpasync16(uint32_t dst, const void* src) {
    asm volatile("cp.async.cg.shared.global [%0], [%1], 16;" :: "r"(dst), "l"(src));
}
#define CP_COMMIT() asm volatile("cp.async.commit_group;" ::: "memory")
#define CP_WAIT0()  asm volatile("cp.async.wait_group 0;" ::: "memory")
#define CP_WAIT2()  asm volatile("cp.async.wait_group 2;" ::: "memory")

__device__ __forceinline__ void ldm4(uint32_t* r, uint32_t addr) {
    asm volatile("ldmatrix.sync.aligned.m8n8.x4.shared.b16 {%0,%1,%2,%3}, [%4];"
                 : "=r"(r[0]), "=r"(r[1]), "=r"(r[2]), "=r"(r[3]) : "r"(addr));
}

__device__ __forceinline__ void mma16816(float* d, const uint32_t* a, const uint32_t* b) {
    asm volatile(
        "mma.sync.aligned.m16n8k16.row.col.f32.f16.f16.f32 "
        "{%0,%1,%2,%3}, {%4,%5,%6,%7}, {%8,%9}, {%0,%1,%2,%3};"
        : "+f"(d[0]), "+f"(d[1]), "+f"(d[2]), "+f"(d[3])
        : "r"(a[0]), "r"(a[1]), "r"(a[2]), "r"(a[3]), "r"(b[0]), "r"(b[1]));
}

// ---------------------------------------------------------------------------
// Single-chain fp16 HMMA NT GEMM: C = A(fp16) * B(fp16)^T + bias.
// CTA 128x128, 8 warps (64Mx32N), k-step 32, FOUR-stage cp.async
// (wait_group 2), 2 CTAs/SM.
//   EPI 0: +bias   1: gelu(+bias)   2: +bias+resid(skip-cls)   3: +bias+C
//   OUT 0: fp32 C  1: fp16 (Ch)
// smem: 4 stages x 20480 B = 81920 B.
// ---------------------------------------------------------------------------
#define STG    20480u
#define OFF_A  0u
#define OFF_B  10240u
#define GEMM_SMEM (4 * STG)

template<int EPI, int OUT>
__global__ void __launch_bounds__(256, 2)
gemm_mma(const __half* __restrict__ Ahg,
         const __half* __restrict__ Bg,
         const float* __restrict__ bias,
         float* __restrict__ C,
         __half* __restrict__ Ch,
         const float* __restrict__ resid,
         int M, int N, int K)
{
    extern __shared__ char smem[];
    const uint32_t sb = smem_u32(smem);

    const int tid  = threadIdx.x;
    const int wid  = tid >> 5;
    const int lane = tid & 31;
    const int row0 = blockIdx.y * 128;
    const int col0 = blockIdx.x * 128;
    const int KT   = K >> 5;

    float acc[4][4][4];
    #pragma unroll
    for (int a = 0; a < 4; a++)
        #pragma unroll
        for (int b = 0; b < 4; b++)
            #pragma unroll
            for (int c = 0; c < 4; c++) acc[a][b][c] = 0.0f;

    auto load_stage = [&](int kt, int buf) {
        const int kw = kt * 32;
        const uint32_t dstb = sb + buf * STG;
        #pragma unroll
        for (int q = 0; q < 2; q++) {
            int cid = q * 256 + tid;
            int row = cid >> 2, ch = cid & 3;
            int ar  = min(row0 + row, M - 1);
            cpasync16(dstb + OFF_A + row * 80u + ch * 16u,
                      Ahg + (size_t)ar * K + kw + ch * 8);
        }
        #pragma unroll
        for (int q = 0; q < 2; q++) {
            int cid = q * 256 + tid;
            int row = cid >> 2, ch = cid & 3;
            cpasync16(dstb + OFF_B + row * 80u + ch * 16u,
                      Bg + (size_t)(col0 + row) * K + kw + ch * 8);
        }
        CP_COMMIT();
    };

    // preload 3 stages (KT >= 24 at every call site)
    load_stage(0, 0);
    load_stage(1, 1);
    load_stage(2, 2);
    CP_WAIT2();                 // stage 0 complete
    __syncthreads();

    const int m0w = (wid & 1) * 64;
    const int n0w = (wid >> 1) * 32;
    const uint32_t a_off = (uint32_t)(m0w + (lane & 15)) * 80u + (uint32_t)((lane >> 4) << 4);
    const uint32_t b_off = (uint32_t)(n0w + (lane & 7) + ((lane >> 4) << 3)) * 80u
                         + (uint32_t)(((lane >> 3) & 1) << 4);

    for (int kt = 0; kt < KT; kt++) {
        const int buf = kt & 3;
        const uint32_t bb = sb + buf * STG;
        #pragma unroll
        for (int s = 0; s < 2; s++) {
            uint32_t ah[4][4], bh[4][2];
            #pragma unroll
            for (int mi = 0; mi < 4; mi++)
                ldm4(ah[mi], bb + OFF_A + a_off + mi * 1280u + s * 32u);
            #pragma unroll
            for (int nj = 0; nj < 2; nj++) {
                uint32_t t[4];
                ldm4(t, bb + OFF_B + b_off + nj * 1280u + s * 32u);
                bh[nj*2][0] = t[0]; bh[nj*2][1] = t[1];
                bh[nj*2+1][0] = t[2]; bh[nj*2+1][1] = t[3];
            }
            #pragma unroll
            for (int mi = 0; mi < 4; mi++)
                #pragma unroll
                for (int nj = 0; nj < 4; nj++)
                    mma16816(acc[mi][nj], ah[mi], bh[nj]);
        }
        if (kt + 3 < KT) {
            load_stage(kt + 3, (kt + 3) & 3);
            CP_WAIT2();         // stage kt+1 complete
        } else {
            CP_WAIT0();
        }
        __syncthreads();
    }

    #pragma unroll
    for (int mi = 0; mi < 4; mi++) {
        const int rbase = row0 + m0w + mi * 16 + (lane >> 2);
        #pragma unroll
        for (int half = 0; half < 2; half++) {
            const int m = rbase + half * 8;
            if (m >= M) continue;
            #pragma unroll
            for (int nj = 0; nj < 4; nj++) {
                const int n = col0 + n0w + nj * 8 + (lane & 3) * 2;
                float v0 = acc[mi][nj][half * 2 + 0] + bias[n];
                float v1 = acc[mi][nj][half * 2 + 1] + bias[n + 1];
                if (EPI == 1) { v0 = gelu_exact(v0); v1 = gelu_exact(v1); }
                if (EPI == 2) {
                    const float* rs = resid + (size_t)(m + m / 1568 + 1) * CC + n;
                    v0 += rs[0]; v1 += rs[1];
                }
                if (OUT == 0) {
                    float* cp = C + (size_t)m * N + n;
                    if (EPI == 3) {
                        float2 old = *(const float2*)cp;
                        v0 += old.x; v1 += old.y;
                    }
                    float2 o = {v0, v1};
                    *(float2*)cp = o;
                } else {
                    *(__half2*)(Ch + (size_t)m * N + n) =
                        __halves2half2(__float2half_rn(v0), __float2half_rn(v1));
                }
            }
        }
    }
}

// ---------------------------------------------------------------------------
// FUSED spatial scores + softmax (1-chain fp16) — Round-12, passing.
// ---------------------------------------------------------------------------
#define FSTG     28160u
#define FOFF_A   0u
#define FOFF_B   10240u
#define FSC_SMEM (2 * FSTG)

__global__ void __launch_bounds__(256)
attn_scores_softmax(const __half* __restrict__ qh, __half* __restrict__ ph)
{
    extern __shared__ char smem[];
    const uint32_t sb = smem_u32(smem);

    const int z = blockIdx.y;
    const int s = z / NH, h = z % NH;
    const size_t base  = (size_t)(s * SL) * C3 + h * HD;
    const size_t pbase = (size_t)z * SL * KP;

    const int tid  = threadIdx.x;
    const int wid  = tid >> 5;
    const int lane = tid & 31;
    const int row0 = blockIdx.x * 128;

    #pragma unroll
    for (int kt = 0; kt < 2; kt++) {
        const int kw = kt * 32;
        const uint32_t dstb = sb + kt * FSTG;
        #pragma unroll
        for (int q = 0; q < 2; q++) {
            int cid = q * 256 + tid;
            int row = cid >> 2, ch = cid & 3;
            int gr  = min(row0 + row, SL - 1);
            cpasync16(dstb + FOFF_A + row * 80u + ch * 16u,
                      qh + base + (size_t)gr * C3 + kw + ch * 8);
        }
        #pragma unroll
        for (int q = 0; q < 4; q++) {
            int cid = q * 256 + tid;
            if (cid < 896) {
                int row = cid >> 2, ch = cid & 3;
                int gr  = min(row, SL - 1);
                cpasync16(dstb + FOFF_B + row * 80u + ch * 16u,
                          qh + base + (size_t)gr * C3 + CC + kw + ch * 8);
            }
        }
        CP_COMMIT();
    }
    CP_WAIT0();
    __syncthreads();

    const int m0w = wid * 16;
    const uint32_t a_off = (uint32_t)(m0w + (lane & 15)) * 80u + (uint32_t)((lane >> 4) << 4);
    const uint32_t b_off = (uint32_t)((lane & 7) + ((lane >> 4) << 3)) * 80u
                         + (uint32_t)(((lane >> 3) & 1) << 4);

    float acc[28][4];
    #pragma unroll
    for (int t = 0; t < 28; t++)
        #pragma unroll
        for (int c = 0; c < 4; c++) acc[t][c] = 0.0f;

    #pragma unroll
    for (int kt = 0; kt < 2; kt++) {
        const uint32_t bb = sb + kt * FSTG;
        #pragma unroll
        for (int s2 = 0; s2 < 2; s2++) {
            uint32_t ah[4];
            ldm4(ah, bb + FOFF_A + a_off + s2 * 32u);
            #pragma unroll
            for (int njq = 0; njq < 14; njq++) {
                uint32_t th[4];
                ldm4(th, bb + FOFF_B + b_off + njq * 1280u + s2 * 32u);
                uint32_t b0[2] = {th[0], th[1]}, b1[2] = {th[2], th[3]};
                mma16816(acc[njq*2],   ah, b0);
                mma16816(acc[njq*2+1], ah, b1);
            }
        }
    }

    const int ncol0 = (lane & 3) * 2;
    #pragma unroll
    for (int half = 0; half < 2; half++) {
        const int row = row0 + m0w + (lane >> 2) + half * 8;
        float mx = -1e30f;
        #pragma unroll
        for (int t = 0; t < 28; t++) {
            int n = t * 8 + ncol0;
            float v0 = acc[t][half*2+0] * 0.125f;
            float v1 = acc[t][half*2+1] * 0.125f;
            acc[t][half*2+0] = (n < SL)     ? v0 : -1e30f;
            acc[t][half*2+1] = (n + 1 < SL) ? v1 : -1e30f;
            mx = fmaxf(mx, acc[t][half*2+0]);
            mx = fmaxf(mx, acc[t][half*2+1]);
        }
        mx = fmaxf(mx, __shfl_xor_sync(0xffffffffu, mx, 1));
        mx = fmaxf(mx, __shfl_xor_sync(0xffffffffu, mx, 2));
        float sum = 0.0f;
        #pragma unroll
        for (int t = 0; t < 28; t++) {
            float e0 = expf(acc[t][half*2+0] - mx);
            float e1 = expf(acc[t][half*2+1] - mx);
            int n = t * 8 + ncol0;
            e0 = (n < SL)     ? e0 : 0.0f;
            e1 = (n + 1 < SL) ? e1 : 0.0f;
            acc[t][half*2+0] = e0;
            acc[t][half*2+1] = e1;
            sum += e0 + e1;
        }
        sum += __shfl_xor_sync(0xffffffffu, sum, 1);
        sum += __shfl_xor_sync(0xffffffffu, sum, 2);
        float inv = 1.0f / sum;
        if (row < SL) {
            size_t ob = pbase + (size_t)row * KP;
            #pragma unroll
            for (int t = 0; t < 28; t++) {
                int n = t * 8 + ncol0;
                *(__half2*)(ph + ob + n) = __halves2half2(
                    __float2half_rn(acc[t][half*2+0] * inv),
                    __float2half_rn(acc[t][half*2+1] * inv));
            }
        }
    }
}

// ---------------------------------------------------------------------------
// Batched PV via HMMA (1-chain fp16) — Round-12, passing.
// ---------------------------------------------------------------------------
#define PSTG    15360u
#define POFF_A  0u
#define POFF_B  10240u
#define PV_SMEM (2 * PSTG)

__global__ void __launch_bounds__(256)
attn_pv_mma(const __half* __restrict__ ph,
            const __half* __restrict__ vth,
            __half* __restrict__ oh)
{
    extern __shared__ char smem[];
    const uint32_t sb = smem_u32(smem);

    const int z = blockIdx.y;
    const int s = z / NH, h = z % NH;
    const size_t pbase = (size_t)z * SL * KP;
    const size_t vbase = (size_t)z * HD * KP;

    const int tid  = threadIdx.x;
    const int wid  = tid >> 5;
    const int lane = tid & 31;
    const int row0 = blockIdx.x * 128;

    float acc[2][4][4];
    #pragma unroll
    for (int a = 0; a < 2; a++)
        #pragma unroll
        for (int b = 0; b < 4; b++)
            #pragma unroll
            for (int c = 0; c < 4; c++) acc[a][b][c] = 0.0f;

    auto load_stage = [&](int kt, int buf) {
        const int kw = kt * 32;
        const uint32_t dstb = sb + buf * PSTG;
        #pragma unroll
        for (int q = 0; q < 2; q++) {
            int cid = q * 256 + tid;
            int row = cid >> 2, ch = cid & 3;
            int gr  = min(row0 + row, SL - 1);
            cpasync16(dstb + POFF_A + row * 80u + ch * 16u,
                      ph + pbase + (size_t)gr * KP + kw + ch * 8);
        }
        {
            int row = tid >> 2, ch = tid & 3;
            cpasync16(dstb + POFF_B + row * 80u + ch * 16u,
                      vth + vbase + (size_t)row * KP + kw + ch * 8);
        }
        CP_COMMIT();
    };

    load_stage(0, 0);
    CP_WAIT0();
    __syncthreads();

    const int m0w = (wid & 3) * 32;
    const int n0w = (wid >> 2) * 32;
    const uint32_t a_off = (uint32_t)(m0w + (lane & 15)) * 80u + (uint32_t)((lane >> 4) << 4);
    const uint32_t b_off = (uint32_t)(n0w + (lane & 7) + ((lane >> 4) << 3)) * 80u
                         + (uint32_t)(((lane >> 3) & 1) << 4);

    for (int kt = 0; kt < KP / 32; kt++) {
        const int buf = kt & 1;
        if (kt + 1 < KP / 32) load_stage(kt + 1, buf ^ 1);

        const uint32_t bb = sb + buf * PSTG;
        #pragma unroll
        for (int s2 = 0; s2 < 2; s2++) {
            uint32_t ah[2][4], bh[4][2];
            #pragma unroll
            for (int mi = 0; mi < 2; mi++)
                ldm4(ah[mi], bb + POFF_A + a_off + mi * 1280u + s2 * 32u);
            #pragma unroll
            for (int nj = 0; nj < 2; nj++) {
                uint32_t t[4];
                ldm4(t, bb + POFF_B + b_off + nj * 1280u + s2 * 32u);
                bh[nj*2][0] = t[0]; bh[nj*2][1] = t[1];
                bh[nj*2+1][0] = t[2]; bh[nj*2+1][1] = t[3];
            }
            #pragma unroll
            for (int mi = 0; mi < 2; mi++)
                #pragma unroll
                for (int nj = 0; nj < 4; nj++)
                    mma16816(acc[mi][nj], ah[mi], bh[nj]);
        }
        CP_WAIT0();
        __syncthreads();
    }

    #pragma unroll
    for (int mi = 0; mi < 2; mi++) {
        const int rbase = row0 + m0w + mi * 16 + (lane >> 2);
        #pragma unroll
        for (int half = 0; half < 2; half++) {
            const int m = rbase + half * 8;
            if (m >= SL) continue;
            size_t ob = (size_t)(s * SL + m) * CC + h * HD;
            #pragma unroll
            for (int nj = 0; nj < 4; nj++) {
                const int n = n0w + nj * 8 + (lane & 3) * 2;
                *(__half2*)(oh + ob + n) = __halves2half2(
                    __float2half_rn(acc[mi][nj][half * 2 + 0]),
                    __float2half_rn(acc[mi][nj][half * 2 + 1]));
            }
        }
    }
}

// ---------------------------------------------------------------------------
// V transpose: per z, Vt[d][t] = V[t][d], padded t->224 with zeros.
// ---------------------------------------------------------------------------
__global__ void transpose_v(const __half* __restrict__ qh, __half* __restrict__ vth)
{
    int z = blockIdx.x;
    int s = z / NH, h = z % NH;
    size_t vbase = (size_t)(s * SL) * C3 + 2 * CC + h * HD;
    size_t obase = (size_t)z * HD * KP;
    __shared__ __half shh[32][66];
    int tid = threadIdx.x;

    for (int t0 = 0; t0 < KP; t0 += 32) {
        #pragma unroll
        for (int i = 0; i < 8; i++) {
            int e = i * 256 + tid;
            int t = e >> 6, d = e & 63;
            int gt = t0 + t;
            shh[t][d] = (gt < SL) ? qh[vbase + (size_t)gt * C3 + d]
                                  : __float2half(0.0f);
        }
        __syncthreads();
        #pragma unroll
        for (int i = 0; i < 8; i++) {
            int e = i * 256 + tid;
            int d = e >> 5, t = e & 31;
            vth[obase + (size_t)d * KP + t0 + t] = shh[t][d];
        }
        __syncthreads();
    }
}

// ---------------------------------------------------------------------------
// Fused weight conversion: 7 weights -> single fp16, one launch.
// ---------------------------------------------------------------------------
struct WSegs {
    const float4* src[7];
    __half2*      dh[7];
    int           n4[7];
};

__global__ void conv_all(WSegs w, int total4)
{
    int i = blockIdx.x * blockDim.x + threadIdx.x;
    if (i >= total4) return;
    int rem = i;
    #pragma unroll
    for (int s = 0; s < 7; s++) {
        if (rem < w.n4[s]) {
            float4 v = w.src[s][rem];
            w.dh[s][rem * 2 + 0] = __halves2half2(__float2half_rn(v.x), __float2half_rn(v.y));
            w.dh[s][rem * 2 + 1] = __halves2half2(__float2half_rn(v.z), __float2half_rn(v.w));
            return;
        }
        rem -= w.n4[s];
    }
}

// ---------------------------------------------------------------------------
// LN core: values v0,v1,v2 per thread. Writes fp16.
// ---------------------------------------------------------------------------
__device__ __forceinline__ void ln_core(float v0, float v1, float v2,
                                        const float* __restrict__ g,
                                        const float* __restrict__ bta,
                                        __half* __restrict__ oh, size_t ob)
{
    int tid = threadIdx.x;
    int lane = tid & 31, wid = tid >> 5;
    __shared__ float sh[32];
    float s = v0 + v1 + v2;
    #pragma unroll
    for (int o = 16; o; o >>= 1) s += __shfl_xor_sync(0xffffffffu, s, o);
    if (lane == 0) sh[wid] = s;
    __syncthreads();
    if (wid == 0) {
        float t2 = (lane < 8) ? sh[lane] : 0.0f;
        #pragma unroll
        for (int o = 4; o; o >>= 1) t2 += __shfl_xor_sync(0xffffffffu, t2, o);
        if (lane == 0) sh[0] = t2;
    }
    __syncthreads();
    float mean = sh[0] * (1.0f / 768.0f);
    __syncthreads();
    float d0 = v0 - mean, d1 = v1 - mean, d2 = v2 - mean;
    float s2 = d0 * d0 + d1 * d1 + d2 * d2;
    #pragma unroll
    for (int o = 16; o; o >>= 1) s2 += __shfl_xor_sync(0xffffffffu, s2, o);
    if (lane == 0) sh[wid] = s2;
    __syncthreads();
    if (wid == 0) {
        float t2 = (lane < 8) ? sh[lane] : 0.0f;
        #pragma unroll
        for (int o = 4; o; o >>= 1) t2 += __shfl_xor_sync(0xffffffffu, t2, o);
        if (lane == 0) sh[0] = t2;
    }
    __syncthreads();
    float inv = rsqrtf(sh[0] * (1.0f / 768.0f) + 1e-5f);
    #pragma unroll
    for (int p = 0; p < 3; p++) {
        float d = (p == 0) ? d0 : (p == 1) ? d1 : d2;
        int c = tid + p * 256;
        oh[ob + c] = __float2half_rn(d * inv * g[c] + bta[c]);
    }
}

// ---------------------------------------------------------------------------
// LayerNorm (modes 0/1 gather). One block/row. Writes fp16.
// ---------------------------------------------------------------------------
__global__ void ln_kernel(const float* __restrict__ src0,
                          const float* __restrict__ xt,
                          const float* __restrict__ g,
                          const float* __restrict__ bta,
                          __half* __restrict__ oh, int mode)
{
    int m = blockIdx.x;
    const float* src;
    if (mode == 0) {
        src = src0 + (size_t)(m + m / 1568 + 1) * CC;
    } else {
        int sb = m / SL, p = m % SL;
        int b = sb >> 3, t = sb & 7;
        if (p == 0) src = src0 + (size_t)b * NTOK * CC;
        else        src = xt + ((size_t)(b * HW + (p - 1)) * TT + t) * CC;
    }
    int tid = threadIdx.x;
    float v0 = src[tid], v1 = src[tid + 256], v2 = src[tid + 512];
    ln_core(v0, v1, v2, g, bta, oh, (size_t)m * CC);
}

// ---------------------------------------------------------------------------
// Fused assemble + LN2 (spatial proj input is fp16).
// ---------------------------------------------------------------------------
__global__ void assemble_ln(const float* __restrict__ x, const float* __restrict__ xt,
                            const __half* __restrict__ ps,
                            const float* __restrict__ g, const float* __restrict__ bta,
                            float* __restrict__ out,
                            __half* __restrict__ oh)
{
    int row = blockIdx.x;
    int b = row / NTOK, n = row % NTOK;
    size_t orow = (size_t)row * CC;
    int tid = threadIdx.x;
    float v[3];
    if (n == 0) {
        #pragma unroll
        for (int p = 0; p < 3; p++) {
            int c = tid + p * 256;
            float acc = 0.0f;
            #pragma unroll
            for (int t = 0; t < TT; t++)
                acc += __half2float(ps[((size_t)(b * TT + t) * SL) * CC + c]);
            v[p] = x[orow + c] + acc * 0.125f;
        }
    } else {
        int r = n - 1, hw = r >> 3, t = r & 7;
        size_t xtrow = ((size_t)b * 1568 + r) * CC;
        size_t psrow = ((size_t)((b * TT + t) * SL + 1 + hw)) * CC;
        #pragma unroll
        for (int p = 0; p < 3; p++) {
            int c = tid + p * 256;
            v[p] = xt[xtrow + c] + __half2float(ps[psrow + c]);
        }
    }
    #pragma unroll
    for (int p = 0; p < 3; p++)
        out[orow + tid + p * 256] = v[p];
    ln_core(v[0], v[1], v[2], g, bta, oh, orow);
}

// ---------------------------------------------------------------------------
// Temporal attention: fused per (seq, head), fp16 qkv input, fp16 output.
// ---------------------------------------------------------------------------
__global__ void temporal_attn(const __half* __restrict__ qkv,
                              __half* __restrict__ oh)
{
    int seq = blockIdx.x, h = blockIdx.y;
    __shared__ float q[TT][68], k[TT][68], v[TT][68];
    __shared__ float p[TT][TT];
    int tid = threadIdx.x;
    size_t base = (size_t)(seq * TT) * C3 + h * HD;

    {
        int t = tid >> 3, d8 = (tid & 7) << 3;
        #pragma unroll
        for (int arr = 0; arr < 3; arr++) {
            float (*dst)[68] = (arr == 0) ? q : (arr == 1) ? k : v;
            float4 raw = *(const float4*)(qkv + base + (size_t)t * C3 + arr * CC + d8);
            const __half2* hp = (const __half2*)&raw;
            #pragma unroll
            for (int u = 0; u < 4; u++) {
                float2 f = __half22float2(hp[u]);
                dst[t][d8 + u * 2]     = f.x;
                dst[t][d8 + u * 2 + 1] = f.y;
            }
        }
    }
    __syncthreads();
    int i = tid >> 3, j = tid & 7;
    float s = 0.0f;
    #pragma unroll
    for (int d = 0; d < HD; d++) s = fmaf(q[i][d], k[j][d], s);
    p[i][j] = s * 0.125f;
    __syncthreads();
    if (tid < TT) {
        float mx = -1e30f;
        #pragma unroll
        for (int jj = 0; jj < TT; jj++) mx = fmaxf(mx, p[tid][jj]);
        float sum = 0.0f;
        #pragma unroll
        for (int jj = 0; jj < TT; jj++) {
            float e = expf(p[tid][jj] - mx);
            p[tid][jj] = e; sum += e;
        }
        float invs = 1.0f / sum;
        #pragma unroll
        for (int jj = 0; jj < TT; jj++) p[tid][jj] *= invs;
    }
    __syncthreads();
    #pragma unroll
    for (int t = 0; t < TT; t++) {
        float o = 0.0f;
        #pragma unroll
        for (int jj = 0; jj < TT; jj++) o = fmaf(p[t][jj], v[jj][tid], o);
        oh[(size_t)(seq * TT + t) * CC + h * HD + tid] = __float2half_rn(o);
    }
}

// ---------------------------------------------------------------------------
// Host launch
// ---------------------------------------------------------------------------
extern "C" void kernel_launch(void* const* d_in, const int* in_sizes, int n_in,
                              void* d_out, int out_size)
{
    const float* x        = (const float*)d_in[0];
    const float* ln_t_g   = (const float*)d_in[1];
    const float* ln_t_b   = (const float*)d_in[2];
    const float* t_qkv_w  = (const float*)d_in[3];
    const float* t_qkv_b  = (const float*)d_in[4];
    const float* t_proj_w = (const float*)d_in[5];
    const float* t_proj_b = (const float*)d_in[6];
    const float* t_fc_w   = (const float*)d_in[7];
    const float* t_fc_b   = (const float*)d_in[8];
    const float* ln1_g    = (const float*)d_in[9];
    const float* ln1_b    = (const float*)d_in[10];
    const float* s_qkv_w  = (const float*)d_in[11];
    const float* s_qkv_b  = (const float*)d_in[12];
    const float* s_proj_w = (const float*)d_in[13];
    const float* s_proj_b = (const float*)d_in[14];
    const float* ln2_g    = (const float*)d_in[15];
    const float* ln2_b    = (const float*)d_in[16];
    const float* fc1_w    = (const float*)d_in[17];
    const float* fc1_b    = (const float*)d_in[18];
    const float* fc2_w    = (const float*)d_in[19];
    const float* fc2_b    = (const float*)d_in[20];
    float* out = (float*)d_out;

    float *xt;
    __half *lnh, *ath, *pjh, *f1h, *qsh, *ph, *vth;
    cudaGetSymbolAddress((void**)&xt,   g_xt);
    cudaGetSymbolAddress((void**)&lnh,  g_ln_h);
    cudaGetSymbolAddress((void**)&ath,  g_at_h);
    cudaGetSymbolAddress((void**)&pjh,  g_pj_h);
    cudaGetSymbolAddress((void**)&f1h,  g_f1_h);
    cudaGetSymbolAddress((void**)&qsh,  g_qs_h);
    cudaGetSymbolAddress((void**)&ph,   g_p_h);
    cudaGetSymbolAddress((void**)&vth,  g_vt_h);

    __half *wtq, *wtp, *wtf, *wsq, *wsp, *wf1, *wf2;
    cudaGetSymbolAddress((void**)&wtq, g_wtq);
    cudaGetSymbolAddress((void**)&wtp, g_wtp);
    cudaGetSymbolAddress((void**)&wtf, g_wtf);
    cudaGetSymbolAddress((void**)&wsq, g_wsq);
    cudaGetSymbolAddress((void**)&wsp, g_wsp);
    cudaGetSymbolAddress((void**)&wf1, g_wf1);
    cudaGetSymbolAddress((void**)&wf2, g_wf2);

    cudaFuncSetAttribute(gemm_mma<0,1>, cudaFuncAttributeMaxDynamicSharedMemorySize, GEMM_SMEM);
    cudaFuncSetAttribute(gemm_mma<1,1>, cudaFuncAttributeMaxDynamicSharedMemorySize, GEMM_SMEM);
    cudaFuncSetAttribute(gemm_mma<2,0>, cudaFuncAttributeMaxDynamicSharedMemorySize, GEMM_SMEM);
    cudaFuncSetAttribute(gemm_mma<3,0>, cudaFuncAttributeMaxDynamicSharedMemorySize, GEMM_SMEM);
    cudaFuncSetAttribute(attn_scores_softmax, cudaFuncAttributeMaxDynamicSharedMemorySize, FSC_SMEM);
    cudaFuncSetAttribute(attn_pv_mma, cudaFuncAttributeMaxDynamicSharedMemorySize, PV_SMEM);

    // 0. convert all 7 weights in one launch (single fp16)
    {
        WSegs w;
        w.src[0] = (const float4*)t_qkv_w;  w.dh[0] = (__half2*)wtq; w.n4[0] = C3 * CC / 4;
        w.src[1] = (const float4*)t_proj_w; w.dh[1] = (__half2*)wtp; w.n4[1] = CC * CC / 4;
        w.src[2] = (const float4*)t_fc_w;   w.dh[2] = (__half2*)wtf; w.n4[2] = CC * CC / 4;
        w.src[3] = (const float4*)s_qkv_w;  w.dh[3] = (__half2*)wsq; w.n4[3] = C3 * CC / 4;
        w.src[4] = (const float4*)s_proj_w; w.dh[4] = (__half2*)wsp; w.n4[4] = CC * CC / 4;
        w.src[5] = (const float4*)fc1_w;    w.dh[5] = (__half2*)wf1; w.n4[5] = HIDDEN * CC / 4;
        w.src[6] = (const float4*)fc2_w;    w.dh[6] = (__half2*)wf2; w.n4[6] = CC * HIDDEN / 4;
        int total4 = 0;
        for (int i = 0; i < 7; i++) total4 += w.n4[i];
        conv_all<<<(total4 + 255) / 256, 256>>>(w, total4);
    }

    // 1. temporal LN (skip cls) -> fp16
    ln_kernel<<<MT, 256>>>(x, nullptr, ln_t_g, ln_t_b, lnh, 0);

    // 2. temporal qkv -> fp16 (qsh buffer)
    gemm_mma<0,1><<<dim3(C3/128, (MT+127)/128), 256, GEMM_SMEM>>>(
        lnh, wtq, t_qkv_b, nullptr, qsh, nullptr, MT, C3, CC);

    // 3. temporal attention -> fp16
    temporal_attn<<<dim3(BB * HW, NH), 64>>>(qsh, ath);

    // 4. temporal proj -> fp16
    gemm_mma<0,1><<<dim3(CC/128, (MT+127)/128), 256, GEMM_SMEM>>>(
        ath, wtp, t_proj_b, nullptr, pjh, nullptr, MT, CC, CC);

    // 5. t_fc + residual from x (skip-cls) -> fp32 xt
    gemm_mma<2,0><<<dim3(CC/128, (MT+127)/128), 256, GEMM_SMEM>>>(
        pjh, wtf, t_fc_b, xt, nullptr, x, MT, CC, CC);

    // 6. spatial gather + LN1 -> fp16
    ln_kernel<<<MS, 256>>>(x, xt, ln1_g, ln1_b, lnh, 1);

    // 7. spatial qkv -> fp16
    gemm_mma<0,1><<<dim3(C3/128, (MS+127)/128), 256, GEMM_SMEM>>>(
        lnh, wsq, s_qkv_b, nullptr, qsh, nullptr, MS, C3, CC);

    // 8-10. spatial attention (tensor cores, 1-chain fp16)
    attn_scores_softmax<<<dim3(2, ZB), 256, FSC_SMEM>>>(qsh, ph);
    transpose_v<<<ZB, 256>>>(qsh, vth);
    attn_pv_mma<<<dim3(2, ZB), 256, PV_SMEM>>>(ph, vth, ath);

    // 11. spatial proj -> fp16 (into pjh; MS rows fit: pjh sized MT*CC < MS*CC?
    //     No — use qsh (free after PV), plenty large: MS*C3.)
    gemm_mma<0,1><<<dim3(CC/128, (MS+127)/128), 256, GEMM_SMEM>>>(
        ath, wsp, s_proj_b, nullptr, qsh, nullptr, MS, CC, CC);

    // 12+13. assemble x_new into d_out AND LN2 -> fp16 (fused)
    assemble_ln<<<MX, 256>>>(x, xt, qsh, ln2_g, ln2_b, out, lnh);

    // 14. fc1 + gelu -> fp16
    gemm_mma<1,1><<<dim3(HIDDEN/128, (MX+127)/128), 256, GEMM_SMEM>>>(
        lnh, wf1, fc1_b, nullptr, f1h, nullptr, MX, HIDDEN, CC);

    // 15. fc2 + in-place residual on d_out
    gemm_mma<3,0><<<dim3(CC/128, (MX+127)/128), 256, GEMM_SMEM>>>(
        f1h, wf2, fc2_b, out, nullptr, nullptr, MX, CC, HIDDEN);
}

// round 15
// speedup vs baseline: 1.1356x; 1.1075x over previous
#include <cuda_runtime.h>
#include <cuda_fp16.h>
#include <math.h>
#include <stdint.h>

// ---------------------------------------------------------------------------
// Problem constants
// ---------------------------------------------------------------------------
#define CC     768
#define C3     2304
#define NH     12
#define HD     64
#define HIDDEN 3072
#define TT     8
#define HW     196
#define BB     4
#define NTOK   1569
#define MT     6272
#define MS     6304
#define MX     6276
#define SL     197
#define SB     32
#define ZB     (SB*NH)
#define KP     224          // padded K for P/Vt (7 * 32)

// ---------------------------------------------------------------------------
// Static device scratch
// ---------------------------------------------------------------------------
__device__ float g_xt [(size_t)MT * CC];

// fp16 activations
__device__ __half g_ln_h[(size_t)MS * CC];
__device__ __half g_at_h[(size_t)MS * CC];
__device__ __half g_pj_h[(size_t)MT * CC];
__device__ __half g_f1_h[(size_t)MX * HIDDEN];
__device__ __half g_qs_h[(size_t)MS * C3];     // qkv (temporal, spatial, proj out)
__device__ __half g_p_h [(size_t)ZB * SL * KP];
__device__ __half g_vt_h[(size_t)ZB * HD * KP];

// weights: single fp16
__device__ __half g_wtq [(size_t)C3 * CC];
__device__ __half g_wtp [(size_t)CC * CC];
__device__ __half g_wtf [(size_t)CC * CC];
__device__ __half g_wsq [(size_t)C3 * CC];
__device__ __half g_wsp [(size_t)CC * CC];
__device__ __half g_wf1 [(size_t)HIDDEN * CC];
__device__ __half g_wf2 [(size_t)CC * HIDDEN];

// ---------------------------------------------------------------------------
// Helpers
// ---------------------------------------------------------------------------
__device__ __forceinline__ float gelu_exact(float v) {
    return 0.5f * v * (1.0f + erff(v * 0.7071067811865475f));
}

__device__ __forceinline__ uint32_t smem_u32(const void* p) {
    uint32_t a;
    asm("{ .reg .u64 t; cvta.to.shared.u64 t, %1; cvt.u32.u64 %0, t; }" : "=r"(a) : "l"(p));
    return a;
}

__device__ __forceinline__ void cpasync16(uint32_t dst, const void* src) {
    asm volatile("cp.async.cg.shared.global [%0], [%1], 16;" :: "r"(dst), "l"(src));
}
#define CP_COMMIT() asm volatile("cp.async.commit_group;" ::: "memory")
#define CP_WAIT0()  asm volatile("cp.async.wait_group 0;" ::: "memory")
#define CP_WAIT1()  asm volatile("cp.async.wait_group 1;" ::: "memory")

__device__ __forceinline__ void ldm4(uint32_t* r, uint32_t addr) {
    asm volatile("ldmatrix.sync.aligned.m8n8.x4.shared.b16 {%0,%1,%2,%3}, [%4];"
                 : "=r"(r[0]), "=r"(r[1]), "=r"(r[2]), "=r"(r[3]) : "r"(addr));
}

__device__ __forceinline__ void mma16816(float* d, const uint32_t* a, const uint32_t* b) {
    asm volatile(
        "mma.sync.aligned.m16n8k16.row.col.f32.f16.f16.f32 "
        "{%0,%1,%2,%3}, {%4,%5,%6,%7}, {%8,%9}, {%0,%1,%2,%3};"
        : "+f"(d[0]), "+f"(d[1]), "+f"(d[2]), "+f"(d[3])
        : "r"(a[0]), "r"(a[1]), "r"(a[2]), "r"(a[3]), "r"(b[0]), "r"(b[1]));
}

// ---------------------------------------------------------------------------
// Single-chain fp16 HMMA NT GEMM: C = A(fp16) * B(fp16)^T + bias.
// CTA 128x128, 8 warps (64Mx32N), k-step 64 (4 x k16 sub-steps), 3-stage
// cp.async (wait_group 1), 2 CTAs/SM. Row pitch 144B (conflict-free ldmatrix).
//   EPI 0: +bias   1: gelu(+bias)   2: +bias+resid(skip-cls)   3: +bias+C
//   OUT 0: fp32 C  1: fp16 (Ch)
// smem: 3 stages x (A 128x144 + B 128x144) = 3 x 36864 = 110592 B.
// Requirements: K % 64 == 0 (768, 3072 ok), KT = K/64 >= 2.
// ---------------------------------------------------------------------------
#define STG    36864u
#define OFF_A  0u
#define OFF_B  18432u
#define GEMM_SMEM (3 * STG)

template<int EPI, int OUT>
__global__ void __launch_bounds__(256, 2)
gemm_mma(const __half* __restrict__ Ahg,
         const __half* __restrict__ Bg,
         const float* __restrict__ bias,
         float* __restrict__ C,
         __half* __restrict__ Ch,
         const float* __restrict__ resid,
         int M, int N, int K)
{
    extern __shared__ char smem[];
    const uint32_t sb = smem_u32(smem);

    const int tid  = threadIdx.x;
    const int wid  = tid >> 5;
    const int lane = tid & 31;
    const int row0 = blockIdx.y * 128;
    const int col0 = blockIdx.x * 128;
    const int KT   = K >> 6;

    float acc[4][4][4];
    #pragma unroll
    for (int a = 0; a < 4; a++)
        #pragma unroll
        for (int b = 0; b < 4; b++)
            #pragma unroll
            for (int c = 0; c < 4; c++) acc[a][b][c] = 0.0f;

    auto load_stage = [&](int kt, int buf) {
        const int kw = kt * 64;
        const uint32_t dstb = sb + buf * STG;
        // A: 128 rows x 8 chunks (16B) = 1024 -> 4 per thread
        #pragma unroll
        for (int q = 0; q < 4; q++) {
            int cid = q * 256 + tid;
            int row = cid >> 3, ch = cid & 7;
            int ar  = min(row0 + row, M - 1);
            cpasync16(dstb + OFF_A + row * 144u + ch * 16u,
                      Ahg + (size_t)ar * K + kw + ch * 8);
        }
        // B: 128 rows x 8 chunks = 1024 -> 4 per thread
        #pragma unroll
        for (int q = 0; q < 4; q++) {
            int cid = q * 256 + tid;
            int row = cid >> 3, ch = cid & 7;
            cpasync16(dstb + OFF_B + row * 144u + ch * 16u,
                      Bg + (size_t)(col0 + row) * K + kw + ch * 8);
        }
        CP_COMMIT();
    };

    load_stage(0, 0);
    load_stage(1, 1);
    CP_WAIT1();                 // stage 0 ready
    __syncthreads();

    const int m0w = (wid & 1) * 64;
    const int n0w = (wid >> 1) * 32;
    const uint32_t a_off = (uint32_t)(m0w + (lane & 15)) * 144u + (uint32_t)((lane >> 4) << 4);
    const uint32_t b_off = (uint32_t)(n0w + (lane & 7) + ((lane >> 4) << 3)) * 144u
                         + (uint32_t)(((lane >> 3) & 1) << 4);

    for (int kt = 0; kt < KT; kt++) {
        const int buf = kt % 3;
        const uint32_t bb = sb + buf * STG;
        #pragma unroll
        for (int s = 0; s < 4; s++) {            // 4 x k16 sub-steps
            uint32_t ah[4][4], bh[4][2];
            #pragma unroll
            for (int mi = 0; mi < 4; mi++)
                ldm4(ah[mi], bb + OFF_A + a_off + mi * 2304u + s * 32u);
            #pragma unroll
            for (int nj = 0; nj < 2; nj++) {
                uint32_t t[4];
                ldm4(t, bb + OFF_B + b_off + nj * 2304u + s * 32u);
                bh[nj*2][0] = t[0]; bh[nj*2][1] = t[1];
                bh[nj*2+1][0] = t[2]; bh[nj*2+1][1] = t[3];
            }
            #pragma unroll
            for (int mi = 0; mi < 4; mi++)
                #pragma unroll
                for (int nj = 0; nj < 4; nj++)
                    mma16816(acc[mi][nj], ah[mi], bh[nj]);
        }
        if (kt + 2 < KT) {
            load_stage(kt + 2, (kt + 2) % 3);    // overwrites stage used at kt-1 (safe: sync'd)
            CP_WAIT1();                          // stage kt+1 ready
        } else {
            CP_WAIT0();
        }
        __syncthreads();
    }

    #pragma unroll
    for (int mi = 0; mi < 4; mi++) {
        const int rbase = row0 + m0w + mi * 16 + (lane >> 2);
        #pragma unroll
        for (int half = 0; half < 2; half++) {
            const int m = rbase + half * 8;
            if (m >= M) continue;
            #pragma unroll
            for (int nj = 0; nj < 4; nj++) {
                const int n = col0 + n0w + nj * 8 + (lane & 3) * 2;
                float v0 = acc[mi][nj][half * 2 + 0] + bias[n];
                float v1 = acc[mi][nj][half * 2 + 1] + bias[n + 1];
                if (EPI == 1) { v0 = gelu_exact(v0); v1 = gelu_exact(v1); }
                if (EPI == 2) {
                    const float* rs = resid + (size_t)(m + m / 1568 + 1) * CC + n;
                    v0 += rs[0]; v1 += rs[1];
                }
                if (OUT == 0) {
                    float* cp = C + (size_t)m * N + n;
                    if (EPI == 3) {
                        float2 old = *(const float2*)cp;
                        v0 += old.x; v1 += old.y;
                    }
                    float2 o = {v0, v1};
                    *(float2*)cp = o;
                } else {
                    *(__half2*)(Ch + (size_t)m * N + n) =
                        __halves2half2(__float2half_rn(v0), __float2half_rn(v1));
                }
            }
        }
    }
}

// ---------------------------------------------------------------------------
// FUSED spatial scores + softmax (1-chain fp16) — Round-12, passing.
// ---------------------------------------------------------------------------
#define FSTG     28160u
#define FOFF_A   0u
#define FOFF_B   10240u
#define FSC_SMEM (2 * FSTG)

__global__ void __launch_bounds__(256)
attn_scores_softmax(const __half* __restrict__ qh, __half* __restrict__ ph)
{
    extern __shared__ char smem[];
    const uint32_t sb = smem_u32(smem);

    const int z = blockIdx.y;
    const int s = z / NH, h = z % NH;
    const size_t base  = (size_t)(s * SL) * C3 + h * HD;
    const size_t pbase = (size_t)z * SL * KP;

    const int tid  = threadIdx.x;
    const int wid  = tid >> 5;
    const int lane = tid & 31;
    const int row0 = blockIdx.x * 128;

    #pragma unroll
    for (int kt = 0; kt < 2; kt++) {
        const int kw = kt * 32;
        const uint32_t dstb = sb + kt * FSTG;
        #pragma unroll
        for (int q = 0; q < 2; q++) {
            int cid = q * 256 + tid;
            int row = cid >> 2, ch = cid & 3;
            int gr  = min(row0 + row, SL - 1);
            cpasync16(dstb + FOFF_A + row * 80u + ch * 16u,
                      qh + base + (size_t)gr * C3 + kw + ch * 8);
        }
        #pragma unroll
        for (int q = 0; q < 4; q++) {
            int cid = q * 256 + tid;
            if (cid < 896) {
                int row = cid >> 2, ch = cid & 3;
                int gr  = min(row, SL - 1);
                cpasync16(dstb + FOFF_B + row * 80u + ch * 16u,
                          qh + base + (size_t)gr * C3 + CC + kw + ch * 8);
            }
        }
        CP_COMMIT();
    }
    CP_WAIT0();
    __syncthreads();

    const int m0w = wid * 16;
    const uint32_t a_off = (uint32_t)(m0w + (lane & 15)) * 80u + (uint32_t)((lane >> 4) << 4);
    const uint32_t b_off = (uint32_t)((lane & 7) + ((lane >> 4) << 3)) * 80u
                         + (uint32_t)(((lane >> 3) & 1) << 4);

    float acc[28][4];
    #pragma unroll
    for (int t = 0; t < 28; t++)
        #pragma unroll
        for (int c = 0; c < 4; c++) acc[t][c] = 0.0f;

    #pragma unroll
    for (int kt = 0; kt < 2; kt++) {
        const uint32_t bb = sb + kt * FSTG;
        #pragma unroll
        for (int s2 = 0; s2 < 2; s2++) {
            uint32_t ah[4];
            ldm4(ah, bb + FOFF_A + a_off + s2 * 32u);
            #pragma unroll
            for (int njq = 0; njq < 14; njq++) {
                uint32_t th[4];
                ldm4(th, bb + FOFF_B + b_off + njq * 1280u + s2 * 32u);
                uint32_t b0[2] = {th[0], th[1]}, b1[2] = {th[2], th[3]};
                mma16816(acc[njq*2],   ah, b0);
                mma16816(acc[njq*2+1], ah, b1);
            }
        }
    }

    const int ncol0 = (lane & 3) * 2;
    #pragma unroll
    for (int half = 0; half < 2; half++) {
        const int row = row0 + m0w + (lane >> 2) + half * 8;
        float mx = -1e30f;
        #pragma unroll
        for (int t = 0; t < 28; t++) {
            int n = t * 8 + ncol0;
            float v0 = acc[t][half*2+0] * 0.125f;
            float v1 = acc[t][half*2+1] * 0.125f;
            acc[t][half*2+0] = (n < SL)     ? v0 : -1e30f;
            acc[t][half*2+1] = (n + 1 < SL) ? v1 : -1e30f;
            mx = fmaxf(mx, acc[t][half*2+0]);
            mx = fmaxf(mx, acc[t][half*2+1]);
        }
        mx = fmaxf(mx, __shfl_xor_sync(0xffffffffu, mx, 1));
        mx = fmaxf(mx, __shfl_xor_sync(0xffffffffu, mx, 2));
        float sum = 0.0f;
        #pragma unroll
        for (int t = 0; t < 28; t++) {
            float e0 = expf(acc[t][half*2+0] - mx);
            float e1 = expf(acc[t][half*2+1] - mx);
            int n = t * 8 + ncol0;
            e0 = (n < SL)     ? e0 : 0.0f;
            e1 = (n + 1 < SL) ? e1 : 0.0f;
            acc[t][half*2+0] = e0;
            acc[t][half*2+1] = e1;
            sum += e0 + e1;
        }
        sum += __shfl_xor_sync(0xffffffffu, sum, 1);
        sum += __shfl_xor_sync(0xffffffffu, sum, 2);
        float inv = 1.0f / sum;
        if (row < SL) {
            size_t ob = pbase + (size_t)row * KP;
            #pragma unroll
            for (int t = 0; t < 28; t++) {
                int n = t * 8 + ncol0;
                *(__half2*)(ph + ob + n) = __halves2half2(
                    __float2half_rn(acc[t][half*2+0] * inv),
                    __float2half_rn(acc[t][half*2+1] * inv));
            }
        }
    }
}

// ---------------------------------------------------------------------------
// Batched PV via HMMA (1-chain fp16) — Round-12, passing.
// ---------------------------------------------------------------------------
#define PSTG    15360u
#define POFF_A  0u
#define POFF_B  10240u
#define PV_SMEM (2 * PSTG)

__global__ void __launch_bounds__(256)
attn_pv_mma(const __half* __restrict__ ph,
            const __half* __restrict__ vth,
            __half* __restrict__ oh)
{
    extern __shared__ char smem[];
    const uint32_t sb = smem_u32(smem);

    const int z = blockIdx.y;
    const int s = z / NH, h = z % NH;
    const size_t pbase = (size_t)z * SL * KP;
    const size_t vbase = (size_t)z * HD * KP;

    const int tid  = threadIdx.x;
    const int wid  = tid >> 5;
    const int lane = tid & 31;
    const int row0 = blockIdx.x * 128;

    float acc[2][4][4];
    #pragma unroll
    for (int a = 0; a < 2; a++)
        #pragma unroll
        for (int b = 0; b < 4; b++)
            #pragma unroll
            for (int c = 0; c < 4; c++) acc[a][b][c] = 0.0f;

    auto load_stage = [&](int kt, int buf) {
        const int kw = kt * 32;
        const uint32_t dstb = sb + buf * PSTG;
        #pragma unroll
        for (int q = 0; q < 2; q++) {
            int cid = q * 256 + tid;
            int row = cid >> 2, ch = cid & 3;
            int gr  = min(row0 + row, SL - 1);
            cpasync16(dstb + POFF_A + row * 80u + ch * 16u,
                      ph + pbase + (size_t)gr * KP + kw + ch * 8);
        }
        {
            int row = tid >> 2, ch = tid & 3;
            cpasync16(dstb + POFF_B + row * 80u + ch * 16u,
                      vth + vbase + (size_t)row * KP + kw + ch * 8);
        }
        CP_COMMIT();
    };

    load_stage(0, 0);
    CP_WAIT0();
    __syncthreads();

    const int m0w = (wid & 3) * 32;
    const int n0w = (wid >> 2) * 32;
    const uint32_t a_off = (uint32_t)(m0w + (lane & 15)) * 80u + (uint32_t)((lane >> 4) << 4);
    const uint32_t b_off = (uint32_t)(n0w + (lane & 7) + ((lane >> 4) << 3)) * 80u
                         + (uint32_t)(((lane >> 3) & 1) << 4);

    for (int kt = 0; kt < KP / 32; kt++) {
        const int buf = kt & 1;
        if (kt + 1 < KP / 32) load_stage(kt + 1, buf ^ 1);

        const uint32_t bb = sb + buf * PSTG;
        #pragma unroll
        for (int s2 = 0; s2 < 2; s2++) {
            uint32_t ah[2][4], bh[4][2];
            #pragma unroll
            for (int mi = 0; mi < 2; mi++)
                ldm4(ah[mi], bb + POFF_A + a_off + mi * 1280u + s2 * 32u);
            #pragma unroll
            for (int nj = 0; nj < 2; nj++) {
                uint32_t t[4];
                ldm4(t, bb + POFF_B + b_off + nj * 1280u + s2 * 32u);
                bh[nj*2][0] = t[0]; bh[nj*2][1] = t[1];
                bh[nj*2+1][0] = t[2]; bh[nj*2+1][1] = t[3];
            }
            #pragma unroll
            for (int mi = 0; mi < 2; mi++)
                #pragma unroll
                for (int nj = 0; nj < 4; nj++)
                    mma16816(acc[mi][nj], ah[mi], bh[nj]);
        }
        CP_WAIT0();
        __syncthreads();
    }

    #pragma unroll
    for (int mi = 0; mi < 2; mi++) {
        const int rbase = row0 + m0w + mi * 16 + (lane >> 2);
        #pragma unroll
        for (int half = 0; half < 2; half++) {
            const int m = rbase + half * 8;
            if (m >= SL) continue;
            size_t ob = (size_t)(s * SL + m) * CC + h * HD;
            #pragma unroll
            for (int nj = 0; nj < 4; nj++) {
                const int n = n0w + nj * 8 + (lane & 3) * 2;
                *(__half2*)(oh + ob + n) = __halves2half2(
                    __float2half_rn(acc[mi][nj][half * 2 + 0]),
                    __float2half_rn(acc[mi][nj][half * 2 + 1]));
            }
        }
    }
}

// ---------------------------------------------------------------------------
// V transpose: per z, Vt[d][t] = V[t][d], padded t->224 with zeros.
// Vectorized gather loads (8 halves per thread).
// ---------------------------------------------------------------------------
__global__ void transpose_v(const __half* __restrict__ qh, __half* __restrict__ vth)
{
    int z = blockIdx.x;
    int s = z / NH, h = z % NH;
    size_t vbase = (size_t)(s * SL) * C3 + 2 * CC + h * HD;
    size_t obase = (size_t)z * HD * KP;
    __shared__ __half shh[32][72];
    int tid = threadIdx.x;

    for (int t0 = 0; t0 < KP; t0 += 32) {
        {
            int t = tid >> 3, ch = tid & 7;      // 32 rows x 8 chunks of 8 halves
            int gt = t0 + t;
            if (gt < SL) {
                float4 raw = *(const float4*)(qh + vbase + (size_t)gt * C3 + ch * 8);
                *(float4*)&shh[t][ch * 8] = raw;
            } else {
                float4 zz = {0.f, 0.f, 0.f, 0.f};
                *(float4*)&shh[t][ch * 8] = zz;
            }
        }
        __syncthreads();
        #pragma unroll
        for (int i = 0; i < 8; i++) {
            int e = i * 256 + tid;
            int d = e >> 5, t = e & 31;
            vth[obase + (size_t)d * KP + t0 + t] = shh[t][d];
        }
        __syncthreads();
    }
}

// ---------------------------------------------------------------------------
// Fused weight conversion: 7 weights -> single fp16, one launch.
// ---------------------------------------------------------------------------
struct WSegs {
    const float4* src[7];
    __half2*      dh[7];
    int           n4[7];
};

__global__ void conv_all(WSegs w, int total4)
{
    int i = blockIdx.x * blockDim.x + threadIdx.x;
    if (i >= total4) return;
    int rem = i;
    #pragma unroll
    for (int s = 0; s < 7; s++) {
        if (rem < w.n4[s]) {
            float4 v = w.src[s][rem];
            w.dh[s][rem * 2 + 0] = __halves2half2(__float2half_rn(v.x), __float2half_rn(v.y));
            w.dh[s][rem * 2 + 1] = __halves2half2(__float2half_rn(v.z), __float2half_rn(v.w));
            return;
        }
        rem -= w.n4[s];
    }
}

// ---------------------------------------------------------------------------
// LN core: values v0,v1,v2 per thread. Writes fp16.
// ---------------------------------------------------------------------------
__device__ __forceinline__ void ln_core(float v0, float v1, float v2,
                                        const float* __restrict__ g,
                                        const float* __restrict__ bta,
                                        __half* __restrict__ oh, size_t ob)
{
    int tid = threadIdx.x;
    int lane = tid & 31, wid = tid >> 5;
    __shared__ float sh[32];
    float s = v0 + v1 + v2;
    #pragma unroll
    for (int o = 16; o; o >>= 1) s += __shfl_xor_sync(0xffffffffu, s, o);
    if (lane == 0) sh[wid] = s;
    __syncthreads();
    if (wid == 0) {
        float t2 = (lane < 8) ? sh[lane] : 0.0f;
        #pragma unroll
        for (int o = 4; o; o >>= 1) t2 += __shfl_xor_sync(0xffffffffu, t2, o);
        if (lane == 0) sh[0] = t2;
    }
    __syncthreads();
    float mean = sh[0] * (1.0f / 768.0f);
    __syncthreads();
    float d0 = v0 - mean, d1 = v1 - mean, d2 = v2 - mean;
    float s2 = d0 * d0 + d1 * d1 + d2 * d2;
    #pragma unroll
    for (int o = 16; o; o >>= 1) s2 += __shfl_xor_sync(0xffffffffu, s2, o);
    if (lane == 0) sh[wid] = s2;
    __syncthreads();
    if (wid == 0) {
        float t2 = (lane < 8) ? sh[lane] : 0.0f;
        #pragma unroll
        for (int o = 4; o; o >>= 1) t2 += __shfl_xor_sync(0xffffffffu, t2, o);
        if (lane == 0) sh[0] = t2;
    }
    __syncthreads();
    float inv = rsqrtf(sh[0] * (1.0f / 768.0f) + 1e-5f);
    #pragma unroll
    for (int p = 0; p < 3; p++) {
        float d = (p == 0) ? d0 : (p == 1) ? d1 : d2;
        int c = tid + p * 256;
        oh[ob + c] = __float2half_rn(d * inv * g[c] + bta[c]);
    }
}

// ---------------------------------------------------------------------------
// LayerNorm (modes 0/1 gather). One block/row. Writes fp16.
// ---------------------------------------------------------------------------
__global__ void ln_kernel(const float* __restrict__ src0,
                          const float* __restrict__ xt,
                          const float* __restrict__ g,
                          const float* __restrict__ bta,
                          __half* __restrict__ oh, int mode)
{
    int m = blockIdx.x;
    const float* src;
    if (mode == 0) {
        src = src0 + (size_t)(m + m / 1568 + 1) * CC;
    } else {
        int sb = m / SL, p = m % SL;
        int b = sb >> 3, t = sb & 7;
        if (p == 0) src = src0 + (size_t)b * NTOK * CC;
        else        src = xt + ((size_t)(b * HW + (p - 1)) * TT + t) * CC;
    }
    int tid = threadIdx.x;
    float v0 = src[tid], v1 = src[tid + 256], v2 = src[tid + 512];
    ln_core(v0, v1, v2, g, bta, oh, (size_t)m * CC);
}

// ---------------------------------------------------------------------------
// Fused assemble + LN2 (spatial proj input is fp16).
// ---------------------------------------------------------------------------
__global__ void assemble_ln(const float* __restrict__ x, const float* __restrict__ xt,
                            const __half* __restrict__ ps,
                            const float* __restrict__ g, const float* __restrict__ bta,
                            float* __restrict__ out,
                            __half* __restrict__ oh)
{
    int row = blockIdx.x;
    int b = row / NTOK, n = row % NTOK;
    size_t orow = (size_t)row * CC;
    int tid = threadIdx.x;
    float v[3];
    if (n == 0) {
        #pragma unroll
        for (int p = 0; p < 3; p++) {
            int c = tid + p * 256;
            float acc = 0.0f;
            #pragma unroll
            for (int t = 0; t < TT; t++)
                acc += __half2float(ps[((size_t)(b * TT + t) * SL) * CC + c]);
            v[p] = x[orow + c] + acc * 0.125f;
        }
    } else {
        int r = n - 1, hw = r >> 3, t = r & 7;
        size_t xtrow = ((size_t)b * 1568 + r) * CC;
        size_t psrow = ((size_t)((b * TT + t) * SL + 1 + hw)) * CC;
        #pragma unroll
        for (int p = 0; p < 3; p++) {
            int c = tid + p * 256;
            v[p] = xt[xtrow + c] + __half2float(ps[psrow + c]);
        }
    }
    #pragma unroll
    for (int p = 0; p < 3; p++)
        out[orow + tid + p * 256] = v[p];
    ln_core(v[0], v[1], v[2], g, bta, oh, orow);
}

// ---------------------------------------------------------------------------
// Temporal attention: fused per (seq, head), fp16 qkv input, fp16 output.
// ---------------------------------------------------------------------------
__global__ void temporal_attn(const __half* __restrict__ qkv,
                              __half* __restrict__ oh)
{
    int seq = blockIdx.x, h = blockIdx.y;
    __shared__ float q[TT][68], k[TT][68], v[TT][68];
    __shared__ float p[TT][TT];
    int tid = threadIdx.x;
    size_t base = (size_t)(seq * TT) * C3 + h * HD;

    {
        int t = tid >> 3, d8 = (tid & 7) << 3;
        #pragma unroll
        for (int arr = 0; arr < 3; arr++) {
            float (*dst)[68] = (arr == 0) ? q : (arr == 1) ? k : v;
            float4 raw = *(const float4*)(qkv + base + (size_t)t * C3 + arr * CC + d8);
            const __half2* hp = (const __half2*)&raw;
            #pragma unroll
            for (int u = 0; u < 4; u++) {
                float2 f = __half22float2(hp[u]);
                dst[t][d8 + u * 2]     = f.x;
                dst[t][d8 + u * 2 + 1] = f.y;
            }
        }
    }
    __syncthreads();
    int i = tid >> 3, j = tid & 7;
    float s = 0.0f;
    #pragma unroll
    for (int d = 0; d < HD; d++) s = fmaf(q[i][d], k[j][d], s);
    p[i][j] = s * 0.125f;
    __syncthreads();
    if (tid < TT) {
        float mx = -1e30f;
        #pragma unroll
        for (int jj = 0; jj < TT; jj++) mx = fmaxf(mx, p[tid][jj]);
        float sum = 0.0f;
        #pragma unroll
        for (int jj = 0; jj < TT; jj++) {
            float e = expf(p[tid][jj] - mx);
            p[tid][jj] = e; sum += e;
        }
        float invs = 1.0f / sum;
        #pragma unroll
        for (int jj = 0; jj < TT; jj++) p[tid][jj] *= invs;
    }
    __syncthreads();
    #pragma unroll
    for (int t = 0; t < TT; t++) {
        float o = 0.0f;
        #pragma unroll
        for (int jj = 0; jj < TT; jj++) o = fmaf(p[t][jj], v[jj][tid], o);
        oh[(size_t)(seq * TT + t) * CC + h * HD + tid] = __float2half_rn(o);
    }
}

// ---------------------------------------------------------------------------
// Host launch
// ---------------------------------------------------------------------------
extern "C" void kernel_launch(void* const* d_in, const int* in_sizes, int n_in,
                              void* d_out, int out_size)
{
    const float* x        = (const float*)d_in[0];
    const float* ln_t_g   = (const float*)d_in[1];
    const float* ln_t_b   = (const float*)d_in[2];
    const float* t_qkv_w  = (const float*)d_in[3];
    const float* t_qkv_b  = (const float*)d_in[4];
    const float* t_proj_w = (const float*)d_in[5];
    const float* t_proj_b = (const float*)d_in[6];
    const float* t_fc_w   = (const float*)d_in[7];
    const float* t_fc_b   = (const float*)d_in[8];
    const float* ln1_g    = (const float*)d_in[9];
    const float* ln1_b    = (const float*)d_in[10];
    const float* s_qkv_w  = (const float*)d_in[11];
    const float* s_qkv_b  = (const float*)d_in[12];
    const float* s_proj_w = (const float*)d_in[13];
    const float* s_proj_b = (const float*)d_in[14];
    const float* ln2_g    = (const float*)d_in[15];
    const float* ln2_b    = (const float*)d_in[16];
    const float* fc1_w    = (const float*)d_in[17];
    const float* fc1_b    = (const float*)d_in[18];
    const float* fc2_w    = (const float*)d_in[19];
    const float* fc2_b    = (const float*)d_in[20];
    float* out = (float*)d_out;

    float *xt;
    __half *lnh, *ath, *pjh, *f1h, *qsh, *ph, *vth;
    cudaGetSymbolAddress((void**)&xt,   g_xt);
    cudaGetSymbolAddress((void**)&lnh,  g_ln_h);
    cudaGetSymbolAddress((void**)&ath,  g_at_h);
    cudaGetSymbolAddress((void**)&pjh,  g_pj_h);
    cudaGetSymbolAddress((void**)&f1h,  g_f1_h);
    cudaGetSymbolAddress((void**)&qsh,  g_qs_h);
    cudaGetSymbolAddress((void**)&ph,   g_p_h);
    cudaGetSymbolAddress((void**)&vth,  g_vt_h);

    __half *wtq, *wtp, *wtf, *wsq, *wsp, *wf1, *wf2;
    cudaGetSymbolAddress((void**)&wtq, g_wtq);
    cudaGetSymbolAddress((void**)&wtp, g_wtp);
    cudaGetSymbolAddress((void**)&wtf, g_wtf);
    cudaGetSymbolAddress((void**)&wsq, g_wsq);
    cudaGetSymbolAddress((void**)&wsp, g_wsp);
    cudaGetSymbolAddress((void**)&wf1, g_wf1);
    cudaGetSymbolAddress((void**)&wf2, g_wf2);

    cudaFuncSetAttribute(gemm_mma<0,1>, cudaFuncAttributeMaxDynamicSharedMemorySize, GEMM_SMEM);
    cudaFuncSetAttribute(gemm_mma<1,1>, cudaFuncAttributeMaxDynamicSharedMemorySize, GEMM_SMEM);
    cudaFuncSetAttribute(gemm_mma<2,0>, cudaFuncAttributeMaxDynamicSharedMemorySize, GEMM_SMEM);
    cudaFuncSetAttribute(gemm_mma<3,0>, cudaFuncAttributeMaxDynamicSharedMemorySize, GEMM_SMEM);
    cudaFuncSetAttribute(attn_scores_softmax, cudaFuncAttributeMaxDynamicSharedMemorySize, FSC_SMEM);
    cudaFuncSetAttribute(attn_pv_mma, cudaFuncAttributeMaxDynamicSharedMemorySize, PV_SMEM);

    // 0. convert all 7 weights in one launch (single fp16)
    {
        WSegs w;
        w.src[0] = (const float4*)t_qkv_w;  w.dh[0] = (__half2*)wtq; w.n4[0] = C3 * CC / 4;
        w.src[1] = (const float4*)t_proj_w; w.dh[1] = (__half2*)wtp; w.n4[1] = CC * CC / 4;
        w.src[2] = (const float4*)t_fc_w;   w.dh[2] = (__half2*)wtf; w.n4[2] = CC * CC / 4;
        w.src[3] = (const float4*)s_qkv_w;  w.dh[3] = (__half2*)wsq; w.n4[3] = C3 * CC / 4;
        w.src[4] = (const float4*)s_proj_w; w.dh[4] = (__half2*)wsp; w.n4[4] = CC * CC / 4;
        w.src[5] = (const float4*)fc1_w;    w.dh[5] = (__half2*)wf1; w.n4[5] = HIDDEN * CC / 4;
        w.src[6] = (const float4*)fc2_w;    w.dh[6] = (__half2*)wf2; w.n4[6] = CC * HIDDEN / 4;
        int total4 = 0;
        for (int i = 0; i < 7; i++) total4 += w.n4[i];
        conv_all<<<(total4 + 255) / 256, 256>>>(w, total4);
    }

    // 1. temporal LN (skip cls) -> fp16
    ln_kernel<<<MT, 256>>>(x, nullptr, ln_t_g, ln_t_b, lnh, 0);

    // 2. temporal qkv -> fp16
    gemm_mma<0,1><<<dim3(C3/128, (MT+127)/128), 256, GEMM_SMEM>>>(
        lnh, wtq, t_qkv_b, nullptr, qsh, nullptr, MT, C3, CC);

    // 3. temporal attention -> fp16
    temporal_attn<<<dim3(BB * HW, NH), 64>>>(qsh, ath);

    // 4. temporal proj -> fp16
    gemm_mma<0,1><<<dim3(CC/128, (MT+127)/128), 256, GEMM_SMEM>>>(
        ath, wtp, t_proj_b, nullptr, pjh, nullptr, MT, CC, CC);

    // 5. t_fc + residual from x (skip-cls) -> fp32 xt
    gemm_mma<2,0><<<dim3(CC/128, (MT+127)/128), 256, GEMM_SMEM>>>(
        pjh, wtf, t_fc_b, xt, nullptr, x, MT, CC, CC);

    // 6. spatial gather + LN1 -> fp16
    ln_kernel<<<MS, 256>>>(x, xt, ln1_g, ln1_b, lnh, 1);

    // 7. spatial qkv -> fp16
    gemm_mma<0,1><<<dim3(C3/128, (MS+127)/128), 256, GEMM_SMEM>>>(
        lnh, wsq, s_qkv_b, nullptr, qsh, nullptr, MS, C3, CC);

    // 8-10. spatial attention (tensor cores, 1-chain fp16)
    attn_scores_softmax<<<dim3(2, ZB), 256, FSC_SMEM>>>(qsh, ph);
    transpose_v<<<ZB, 256>>>(qsh, vth);
    attn_pv_mma<<<dim3(2, ZB), 256, PV_SMEM>>>(ph, vth, ath);

    // 11. spatial proj -> fp16 (into qsh, free after PV)
    gemm_mma<0,1><<<dim3(CC/128, (MS+127)/128), 256, GEMM_SMEM>>>(
        ath, wsp, s_proj_b, nullptr, qsh, nullptr, MS, CC, CC);

    // 12+13. assemble x_new into d_out AND LN2 -> fp16 (fused)
    assemble_ln<<<MX, 256>>>(x, xt, qsh, ln2_g, ln2_b, out, lnh);

    // 14. fc1 + gelu -> fp16
    gemm_mma<1,1><<<dim3(HIDDEN/128, (MX+127)/128), 256, GEMM_SMEM>>>(
        lnh, wf1, fc1_b, nullptr, f1h, nullptr, MX, HIDDEN, CC);

    // 15. fc2 + in-place residual on d_out
    gemm_mma<3,0><<<dim3(CC/128, (MX+127)/128), 256, GEMM_SMEM>>>(
        f1h, wf2, fc2_b, out, nullptr, nullptr, MX, CC, HIDDEN);
}